// round 11
// baseline (speedup 1.0000x reference)
#include <cuda_runtime.h>
#include <cuda_bf16.h>
#include <math.h>
#include <stdint.h>

#define CS 1024
#define CZ 128
#define NH 16
#define HD 64
#define NI 1024
#define NJ 1024
#define NELEM (NI * CS)

// ---------------- scratch (device globals; no allocation allowed) ----------------
__device__ float g_g[NELEM];
__device__ float g_z[(size_t)NH * NI * NJ];   // 64 MB

// bf16 hi/lo split buffers (inputs + weights)
__device__ __nv_bfloat16 g_sh[NELEM],  g_sl[NELEM];     // s
__device__ __nv_bfloat16 g_xh[NELEM],  g_xl[NELEM];     // k_in
__device__ __nv_bfloat16 g_wqh[NELEM], g_wql[NELEM];
__device__ __nv_bfloat16 g_wkh[NELEM], g_wkl[NELEM];
__device__ __nv_bfloat16 g_wvh[NELEM], g_wvl[NELEM];
__device__ __nv_bfloat16 g_wgh[NELEM], g_wgl[NELEM];
__device__ __nv_bfloat16 g_woh[NELEM], g_wol[NELEM];
__device__ __nv_bfloat16 g_goh[NELEM], g_gol[NELEM];    // g (*) o  (written by attn epilogue)
// q/k/v hi/lo (written directly by projection epilogue)
__device__ __nv_bfloat16 g_qbh[NELEM], g_qbl[NELEM];
__device__ __nv_bfloat16 g_kbh[NELEM], g_kbl[NELEM];
__device__ __nv_bfloat16 g_vbh[NELEM], g_vbl[NELEM];

// =====================================================================
// helpers (baseline PTX only — NO tcgen05 on this toolchain path)
// =====================================================================
__device__ __forceinline__ uint32_t smem_u32(const void* p) {
    uint32_t a;
    asm("{ .reg .u64 t; cvta.to.shared.u64 t, %1; cvt.u32.u64 %0, t; }"
        : "=r"(a) : "l"(p));
    return a;
}

__device__ __forceinline__ void cp16(uint32_t dst, const void* src) {
    uint64_t g;
    asm("cvta.to.global.u64 %0, %1;" : "=l"(g) : "l"(src));
    asm volatile("cp.async.cg.shared.global [%0], [%1], 16;" :: "r"(dst), "l"(g));
}

__device__ __forceinline__ void ldm_x4(uint32_t* r, uint32_t addr) {
    asm volatile("ldmatrix.sync.aligned.m8n8.x4.shared.b16 {%0,%1,%2,%3}, [%4];"
        : "=r"(r[0]), "=r"(r[1]), "=r"(r[2]), "=r"(r[3]) : "r"(addr));
}

__device__ __forceinline__ void ldm_x4t(uint32_t* r, uint32_t addr) {
    asm volatile("ldmatrix.sync.aligned.m8n8.x4.trans.shared.b16 {%0,%1,%2,%3}, [%4];"
        : "=r"(r[0]), "=r"(r[1]), "=r"(r[2]), "=r"(r[3]) : "r"(addr));
}

__device__ __forceinline__ void mma16816(float* d, const uint32_t* a, const uint32_t* b) {
    asm volatile(
        "mma.sync.aligned.m16n8k16.row.col.f32.bf16.bf16.f32 "
        "{%0,%1,%2,%3}, {%4,%5,%6,%7}, {%8,%9}, {%0,%1,%2,%3};"
        : "+f"(d[0]), "+f"(d[1]), "+f"(d[2]), "+f"(d[3])
        : "r"(a[0]), "r"(a[1]), "r"(a[2]), "r"(a[3]), "r"(b[0]), "r"(b[1]));
}

__device__ __forceinline__ uint32_t swz(uint32_t off) {
    return off ^ ((off >> 3) & 0x70);
}

// FMA-pipe exp (no MUFU): exp(x) = 2^(x*log2e), poly on [-0.5,0.5]
__device__ __forceinline__ float fexp(float x) {
    float t = fmaxf(x * 1.4426950408889634f, -126.0f);
    float zz = t + 12582912.0f;              // 1.5 * 2^23 magic round
    int   ii = __float_as_int(zz) - 0x4B400000;
    float f  = t - (zz - 12582912.0f);
    float p  = 1.3333558146e-3f;
    p = fmaf(p, f, 9.6181291076e-3f);
    p = fmaf(p, f, 5.5504108664e-2f);
    p = fmaf(p, f, 2.4022650696e-1f);
    p = fmaf(p, f, 6.9314718056e-1f);
    p = fmaf(p, f, 1.0f);
    return __int_as_float(__float_as_int(p) + (ii << 23));
}

__device__ __forceinline__ uint32_t pk_hi(float a, float b) {
    __nv_bfloat162 t;
    t.x = __float2bfloat16(a); t.y = __float2bfloat16(b);
    return *(uint32_t*)&t;
}
__device__ __forceinline__ uint32_t pk_lo(float a, float b) {
    __nv_bfloat16 ha = __float2bfloat16(a), hb = __float2bfloat16(b);
    __nv_bfloat162 t;
    t.x = __float2bfloat16(a - __bfloat162float(ha));
    t.y = __float2bfloat16(b - __bfloat162float(hb));
    return *(uint32_t*)&t;
}

// =====================================================================
// split conversion: x -> (hi=bf16(x), lo=bf16(x-hi))
// =====================================================================
struct SplitArgs {
    const float* src[7];
    __nv_bfloat16* hi[7];
    __nv_bfloat16* lo[7];
};

__device__ __forceinline__ void split4(float4 v, __nv_bfloat162* hi2,
                                       __nv_bfloat162* lo2, size_t i) {
    __nv_bfloat16 h0 = __float2bfloat16(v.x);
    __nv_bfloat16 h1 = __float2bfloat16(v.y);
    __nv_bfloat16 h2 = __float2bfloat16(v.z);
    __nv_bfloat16 h3 = __float2bfloat16(v.w);
    __nv_bfloat16 l0 = __float2bfloat16(v.x - __bfloat162float(h0));
    __nv_bfloat16 l1 = __float2bfloat16(v.y - __bfloat162float(h1));
    __nv_bfloat16 l2 = __float2bfloat16(v.z - __bfloat162float(h2));
    __nv_bfloat16 l3 = __float2bfloat16(v.w - __bfloat162float(h3));
    __nv_bfloat162 ph0; ph0.x = h0; ph0.y = h1;
    __nv_bfloat162 ph1; ph1.x = h2; ph1.y = h3;
    __nv_bfloat162 pl0; pl0.x = l0; pl0.y = l1;
    __nv_bfloat162 pl1; pl1.x = l2; pl1.y = l3;
    hi2[2 * i] = ph0; hi2[2 * i + 1] = ph1;
    lo2[2 * i] = pl0; lo2[2 * i + 1] = pl1;
}

__global__ __launch_bounds__(256) void split7(SplitArgs a) {
    const float4* src = (const float4*)a.src[blockIdx.y];
    __nv_bfloat162* hi2 = (__nv_bfloat162*)a.hi[blockIdx.y];
    __nv_bfloat162* lo2 = (__nv_bfloat162*)a.lo[blockIdx.y];
    int t = blockIdx.x * 256 + threadIdx.x;
    for (size_t i = t; i < NELEM / 4; i += 256 * 256)
        split4(src[i], hi2, lo2, i);
}

// =====================================================================
// bf16-split GEMM via mma.sync: 128x128 tiles (projections)
// =====================================================================
#define STAGE_BYTES 65536
#define GEMM_SMEM (3 * STAGE_BYTES + 1024)

__device__ __forceinline__ void load_stage(
    uint32_t sbase, int s, int tid,
    const __nv_bfloat16* Ah, const __nv_bfloat16* Al,
    const __nv_bfloat16* Bh, const __nv_bfloat16* Bl,
    int m0, int n0)
{
    uint32_t sb = sbase + (uint32_t)(s % 3) * STAGE_BYTES;
    int k0 = s * 64;
#pragma unroll
    for (int p = 0; p < 4; p++) {
        int slot = tid + 256 * p;
        int row = slot >> 3;
        int ch = slot & 7;
        uint32_t off = swz((uint32_t)(row * 128 + ch * 16));
        size_t aoff = (size_t)(m0 + row) * CS + k0 + ch * 8;
        size_t boff = (size_t)(n0 + row) * CS + k0 + ch * 8;
        cp16(sb + off,          Ah + aoff);
        cp16(sb + 16384u + off, Al + aoff);
        cp16(sb + 32768u + off, Bh + boff);
        cp16(sb + 49152u + off, Bl + boff);
    }
}

template <int MODE, int OUT>   // MODE: 0 plain,1 +bias,2 sigmoid; OUT: 0 fp32, 1 bf16 hi/lo
__device__ void gemm_mma_core(
    const __nv_bfloat16* Ah, const __nv_bfloat16* Al,
    const __nv_bfloat16* Bh, const __nv_bfloat16* Bl,
    const float* bvec, float* C,
    __nv_bfloat16* Ch, __nv_bfloat16* Cl, int m0, int n0)
{
    extern __shared__ __align__(16) char dsm[];
    const int tid = threadIdx.x;
    uint32_t sbase = smem_u32(dsm);
    sbase = (sbase + 1023u) & ~1023u;

    const int w  = tid >> 5;
    const int ln = tid & 31;
    const int wm = w & 3;
    const int wn = w >> 2;

    float acc[2][8][4];
#pragma unroll
    for (int mt = 0; mt < 2; mt++)
#pragma unroll
        for (int nt = 0; nt < 8; nt++)
#pragma unroll
            for (int e = 0; e < 4; e++) acc[mt][nt][e] = 0.f;

    load_stage(sbase, 0, tid, Ah, Al, Bh, Bl, m0, n0);
    asm volatile("cp.async.commit_group;" ::: "memory");
    load_stage(sbase, 1, tid, Ah, Al, Bh, Bl, m0, n0);
    asm volatile("cp.async.commit_group;" ::: "memory");

    const int a_row = wm * 32 + (ln & 15);
    const int a_kb  = (ln >> 4) * 16;
    const int b_row = wn * 64 + (ln & 7) + ((ln >> 4) & 1) * 8;
    const int b_kb  = ((ln >> 3) & 1) * 16;

    for (int s = 0; s < 16; s++) {
        if (s < 15) asm volatile("cp.async.wait_group 1;" ::: "memory");
        else        asm volatile("cp.async.wait_group 0;" ::: "memory");
        __syncthreads();

        uint32_t sb = sbase + (uint32_t)(s % 3) * STAGE_BYTES;
#pragma unroll
        for (int kk = 0; kk < 4; kk++) {
            uint32_t ah[2][4], al[2][4], bh[8][2], bl[8][2];
#pragma unroll
            for (int mt = 0; mt < 2; mt++) {
                uint32_t off = swz((uint32_t)((a_row + mt * 16) * 128 + kk * 32 + a_kb));
                ldm_x4(ah[mt], sb + off);
                ldm_x4(al[mt], sb + 16384u + off);
            }
#pragma unroll
            for (int np = 0; np < 4; np++) {
                uint32_t off = swz((uint32_t)((b_row + np * 16) * 128 + kk * 32 + b_kb));
                uint32_t t4[4];
                ldm_x4(t4, sb + 32768u + off);
                bh[2 * np][0] = t4[0]; bh[2 * np][1] = t4[1];
                bh[2 * np + 1][0] = t4[2]; bh[2 * np + 1][1] = t4[3];
                ldm_x4(t4, sb + 49152u + off);
                bl[2 * np][0] = t4[0]; bl[2 * np][1] = t4[1];
                bl[2 * np + 1][0] = t4[2]; bl[2 * np + 1][1] = t4[3];
            }
#pragma unroll
            for (int mt = 0; mt < 2; mt++)
#pragma unroll
                for (int nt = 0; nt < 8; nt++) {
                    mma16816(acc[mt][nt], ah[mt], bh[nt]);
                    mma16816(acc[mt][nt], al[mt], bh[nt]);
                    mma16816(acc[mt][nt], ah[mt], bl[nt]);
                }
        }

        if (s + 2 < 16) {
            load_stage(sbase, s + 2, tid, Ah, Al, Bh, Bl, m0, n0);
            asm volatile("cp.async.commit_group;" ::: "memory");
        }
    }

    const int er = ln >> 2;
    const int ec = (ln & 3) * 2;
#pragma unroll
    for (int mt = 0; mt < 2; mt++) {
#pragma unroll
        for (int nt = 0; nt < 8; nt++) {
            int m = m0 + wm * 32 + mt * 16 + er;
            int n = n0 + wn * 64 + nt * 8 + ec;
#pragma unroll
            for (int half = 0; half < 2; half++) {
                float2 r;
                r.x = acc[mt][nt][2 * half + 0];
                r.y = acc[mt][nt][2 * half + 1];
                if (MODE == 1) { r.x += bvec[n]; r.y += bvec[n + 1]; }
                else if (MODE == 2) {
                    r.x = 1.f / (1.f + __expf(-r.x));
                    r.y = 1.f / (1.f + __expf(-r.y));
                }
                size_t idx = (size_t)(m + half * 8) * CS + n;
                if (OUT == 0) {
                    *(float2*)(C + idx) = r;
                } else {
                    __nv_bfloat162 hh, ll;
                    uint32_t uh = pk_hi(r.x, r.y), ul = pk_lo(r.x, r.y);
                    hh = *(__nv_bfloat162*)&uh; ll = *(__nv_bfloat162*)&ul;
                    *(__nv_bfloat162*)(Ch + idx) = hh;
                    *(__nv_bfloat162*)(Cl + idx) = ll;
                }
            }
        }
    }
}

__global__ __launch_bounds__(256, 1) void gemm_tc4(
    const __nv_bfloat16* sh,  const __nv_bfloat16* sl,
    const __nv_bfloat16* xh,  const __nv_bfloat16* xl,
    const __nv_bfloat16* wqh, const __nv_bfloat16* wql,
    const __nv_bfloat16* wkh, const __nv_bfloat16* wkl,
    const __nv_bfloat16* wvh, const __nv_bfloat16* wvl,
    const __nv_bfloat16* wgh, const __nv_bfloat16* wgl,
    const float* bq,
    __nv_bfloat16* qbh, __nv_bfloat16* qbl,
    __nv_bfloat16* kbh, __nv_bfloat16* kbl,
    __nv_bfloat16* vbh, __nv_bfloat16* vbl,
    float* g)
{
    int m0 = blockIdx.y * 128, n0 = blockIdx.x * 128;
    switch (blockIdx.z) {
        case 0:  gemm_mma_core<1, 1>(sh, sl, wqh, wql, bq, nullptr, qbh, qbl, m0, n0); break;
        case 1:  gemm_mma_core<0, 1>(xh, xl, wkh, wkl, nullptr, nullptr, kbh, kbl, m0, n0); break;
        case 2:  gemm_mma_core<0, 1>(xh, xl, wvh, wvl, nullptr, nullptr, vbh, vbl, m0, n0); break;
        default: gemm_mma_core<2, 0>(sh, sl, wgh, wgl, nullptr, g, nullptr, nullptr, m0, n0); break;
    }
}

// =====================================================================
// Output GEMM: BM=64 x BN=128 tiles -> 128 CTAs (one full wave)
// =====================================================================
#define G64_SSZ 49152
#define G64_SMEM (3 * G64_SSZ + 1024)

__device__ __forceinline__ void load_stage64(
    uint32_t sbase, int s, int tid,
    const __nv_bfloat16* Ah, const __nv_bfloat16* Al,
    const __nv_bfloat16* Bh, const __nv_bfloat16* Bl,
    int m0, int n0)
{
    uint32_t sb = sbase + (uint32_t)(s % 3) * G64_SSZ;
    int k0 = s * 64;
#pragma unroll
    for (int p = 0; p < 4; p++) {          // A hi/lo: 64 rows x 8 x 2
        int slot = tid + 256 * p;
        int arr = slot >> 9, idx = slot & 511;
        int row = idx >> 3, ch = idx & 7;
        cp16(sb + (uint32_t)arr * 8192u + swz((uint32_t)(row * 128 + ch * 16)),
             (arr ? Al : Ah) + (size_t)(m0 + row) * CS + k0 + ch * 8);
    }
#pragma unroll
    for (int p = 0; p < 8; p++) {          // B hi/lo: 128 rows x 8 x 2
        int slot = tid + 256 * p;
        int arr = slot >> 10, idx = slot & 1023;
        int row = idx >> 3, ch = idx & 7;
        cp16(sb + 16384u + (uint32_t)arr * 16384u + swz((uint32_t)(row * 128 + ch * 16)),
             (arr ? Bl : Bh) + (size_t)(n0 + row) * CS + k0 + ch * 8);
    }
}

__global__ __launch_bounds__(256, 1) void gemm_out64(
    const __nv_bfloat16* Ah, const __nv_bfloat16* Al,
    const __nv_bfloat16* Bh, const __nv_bfloat16* Bl,
    float* out)
{
    extern __shared__ __align__(16) char dsm[];
    const int tid = threadIdx.x;
    uint32_t sbase = smem_u32(dsm);
    sbase = (sbase + 1023u) & ~1023u;
    const int m0 = blockIdx.y * 64, n0 = blockIdx.x * 128;

    const int w = tid >> 5, ln = tid & 31;
    const int wm = w & 1;        // 2 warps over M (32 rows)
    const int wn = w >> 1;       // 4 warps over N (32 cols)

    float acc[2][4][4];
#pragma unroll
    for (int mt = 0; mt < 2; mt++)
#pragma unroll
        for (int nt = 0; nt < 4; nt++)
#pragma unroll
            for (int e = 0; e < 4; e++) acc[mt][nt][e] = 0.f;

    load_stage64(sbase, 0, tid, Ah, Al, Bh, Bl, m0, n0);
    asm volatile("cp.async.commit_group;" ::: "memory");
    load_stage64(sbase, 1, tid, Ah, Al, Bh, Bl, m0, n0);
    asm volatile("cp.async.commit_group;" ::: "memory");

    const int a_row = wm * 32 + (ln & 15);
    const int a_kb  = (ln >> 4) * 16;
    const int b_row = wn * 32 + (ln & 7) + ((ln >> 4) & 1) * 8;
    const int b_kb  = ((ln >> 3) & 1) * 16;

    for (int s = 0; s < 16; s++) {
        if (s < 15) asm volatile("cp.async.wait_group 1;" ::: "memory");
        else        asm volatile("cp.async.wait_group 0;" ::: "memory");
        __syncthreads();

        uint32_t sb = sbase + (uint32_t)(s % 3) * G64_SSZ;
#pragma unroll
        for (int kk = 0; kk < 4; kk++) {
            uint32_t ah4[2][4], al4[2][4], bh[4][2], bl[4][2];
#pragma unroll
            for (int mt = 0; mt < 2; mt++) {
                uint32_t off = swz((uint32_t)((a_row + mt * 16) * 128 + kk * 32 + a_kb));
                ldm_x4(ah4[mt], sb + off);
                ldm_x4(al4[mt], sb + 8192u + off);
            }
#pragma unroll
            for (int np = 0; np < 2; np++) {
                uint32_t off = swz((uint32_t)((b_row + np * 16) * 128 + kk * 32 + b_kb));
                uint32_t t4[4];
                ldm_x4(t4, sb + 16384u + off);
                bh[2 * np][0] = t4[0]; bh[2 * np][1] = t4[1];
                bh[2 * np + 1][0] = t4[2]; bh[2 * np + 1][1] = t4[3];
                ldm_x4(t4, sb + 32768u + off);
                bl[2 * np][0] = t4[0]; bl[2 * np][1] = t4[1];
                bl[2 * np + 1][0] = t4[2]; bl[2 * np + 1][1] = t4[3];
            }
#pragma unroll
            for (int mt = 0; mt < 2; mt++)
#pragma unroll
                for (int nt = 0; nt < 4; nt++) {
                    mma16816(acc[mt][nt], ah4[mt], bh[nt]);
                    mma16816(acc[mt][nt], al4[mt], bh[nt]);
                    mma16816(acc[mt][nt], ah4[mt], bl[nt]);
                }
        }

        if (s + 2 < 16) {
            load_stage64(sbase, s + 2, tid, Ah, Al, Bh, Bl, m0, n0);
            asm volatile("cp.async.commit_group;" ::: "memory");
        }
    }

    const int er = ln >> 2, ec = (ln & 3) * 2;
#pragma unroll
    for (int mt = 0; mt < 2; mt++)
#pragma unroll
        for (int nt = 0; nt < 4; nt++) {
            int m = m0 + wm * 32 + mt * 16 + er;
            int n = n0 + wn * 32 + nt * 8 + ec;
            float2 r0; r0.x = acc[mt][nt][0]; r0.y = acc[mt][nt][1];
            float2 r1; r1.x = acc[mt][nt][2]; r1.y = acc[mt][nt][3];
            *(float2*)(out + (size_t)m * CS + n) = r0;
            *(float2*)(out + (size_t)(m + 8) * CS + n) = r1;
        }
}

// ---------------- z kernel (unchanged; runs on side stream) ----------------
#define ZB_SMEM ((2 * 256 * 33 + CZ * NH) * 4)
__global__ __launch_bounds__(256) void zbias_kernel(
    const float* __restrict__ bias, const float* __restrict__ Wz,
    const float* __restrict__ mask, float* __restrict__ z)
{
    extern __shared__ float sm[];
    float* bs = sm;
    float* wzs = sm + 2 * 256 * 33;

    const int tid = threadIdx.x;
    const int jg = tid & 31;
    const int hg = (tid >> 5) & 3;
    const int ig = tid >> 7;
    const int i0 = blockIdx.x * 2;
    const int j0 = blockIdx.y * 256;

    for (int t = tid; t < CZ * NH; t += 256) wzs[t] = Wz[t];

    float acc[8][4];
#pragma unroll
    for (int kk = 0; kk < 8; kk++)
#pragma unroll
        for (int hh = 0; hh < 4; hh++) acc[kk][hh] = 0.f;

    for (int cc = 0; cc < CZ; cc += 32) {
        __syncthreads();
#pragma unroll
        for (int p = 0; p < 16; p++) {
            int slot = tid + 256 * p;
            int c4 = slot & 7;
            int row = slot >> 3;
            int ii = row >> 8;
            int j = row & 255;
            float4 vv = *(const float4*)(bias +
                ((size_t)(i0 + ii) * NJ + (j0 + j)) * CZ + cc + c4 * 4);
            float* dst = bs + ((size_t)ii * 256 + j) * 33 + c4 * 4;
            dst[0] = vv.x; dst[1] = vv.y; dst[2] = vv.z; dst[3] = vv.w;
        }
        __syncthreads();

#pragma unroll
        for (int c = 0; c < 32; c++) {
            const float* wrow = wzs + (cc + c) * NH + hg * 4;
            float w0 = wrow[0], w1 = wrow[1], w2 = wrow[2], w3 = wrow[3];
#pragma unroll
            for (int kk = 0; kk < 8; kk++) {
                float bv = bs[((size_t)ig * 256 + (jg + 32 * kk)) * 33 + c];
                acc[kk][0] += bv * w0;
                acc[kk][1] += bv * w1;
                acc[kk][2] += bv * w2;
                acc[kk][3] += bv * w3;
            }
        }
    }

    const int i = i0 + ig;
#pragma unroll
    for (int hh = 0; hh < 4; hh++) {
        int h = hg * 4 + hh;
        size_t base = ((size_t)h * NI + i) * NJ;
#pragma unroll
        for (int kk = 0; kk < 8; kk++) {
            int j = j0 + jg + 32 * kk;
            z[base + j] = acc[kk][hh] + (1.f - mask[j]) * (-1000000.0f);
        }
    }
}

// =====================================================================
// Flash attention v2: CTA = (head, 128 i-rows); warp owns 16 full rows.
// Register softmax (4-lane shuffles), in-register P->A-frag repack (FA2),
// double-buffered cp.async K/V/z, fused g (*) o hi/lo split epilogue.
// =====================================================================
#define AQ_H 0
#define AQ_L 16384
#define ASTG 32768
#define SKH 0
#define SKL 8192
#define SVH 16384
#define SVL 24576
#define SZO 32768
#define SSZ (32768 + 128 * 68 * 4)   /* 67584 */
#define AT_SMEM (ASTG + 2 * SSZ)     /* 167936 */

__device__ __forceinline__ void attn_load_kvz(
    uint32_t sb, int stage, int j0, int h, int i0, int tid,
    const __nv_bfloat16* kh, const __nv_bfloat16* kl,
    const __nv_bfloat16* vh, const __nv_bfloat16* vl,
    const float* z)
{
    uint32_t stg = sb + ASTG + (uint32_t)stage * SSZ;
#pragma unroll
    for (int p = 0; p < 8; p++) {
        int slot = tid + 256 * p;
        int arr = slot >> 9, idx = slot & 511;
        int row = idx >> 3, ch = idx & 7;
        const __nv_bfloat16* base =
            (arr == 0) ? kh : (arr == 1) ? kl : (arr == 2) ? vh : vl;
        cp16(stg + (uint32_t)arr * 8192u + swz((uint32_t)(row * 128 + ch * 16)),
             base + (size_t)(j0 + row) * CS + h * HD + ch * 8);
    }
    // z tile: 128 rows x 64 floats = 2048 x 16B chunks  (FIXED: was 512)
#pragma unroll
    for (int p = 0; p < 8; p++) {
        int slot = tid + 256 * p;
        int row = slot >> 4, c4 = slot & 15;
        cp16(stg + SZO + (uint32_t)(row * 272 + c4 * 16),
             z + ((size_t)h * NI + i0 + row) * NJ + j0 + c4 * 4);
    }
}

__global__ __launch_bounds__(256, 1) void attn_mma(
    const __nv_bfloat16* __restrict__ qh_g, const __nv_bfloat16* __restrict__ ql_g,
    const __nv_bfloat16* __restrict__ kh_g, const __nv_bfloat16* __restrict__ kl_g,
    const __nv_bfloat16* __restrict__ vh_g, const __nv_bfloat16* __restrict__ vl_g,
    const float* __restrict__ z, const float* __restrict__ g,
    __nv_bfloat16* __restrict__ goh, __nv_bfloat16* __restrict__ gol)
{
    extern __shared__ __align__(16) char smra[];
    uint32_t sb = smem_u32(smra);
    const int h = blockIdx.x;
    const int i0 = blockIdx.y * 128;
    const int tid = threadIdx.x;
    const int w = tid >> 5, ln = tid & 31;
    const int r0 = w * 16;               // warp's 16 rows
    const int er = ln >> 2, ec = (ln & 3) * 2;

    // Q hi/lo (128 x 64 bf16 each)
#pragma unroll
    for (int p = 0; p < 8; p++) {
        int slot = tid + 256 * p;
        int arr = slot >> 10, idx = slot & 1023;
        int row = idx >> 3, ch = idx & 7;
        cp16(sb + (arr ? AQ_L : AQ_H) + swz((uint32_t)(row * 128 + ch * 16)),
             (arr ? ql_g : qh_g) + (size_t)(i0 + row) * CS + h * HD + ch * 8);
    }
    attn_load_kvz(sb, 0, 0, h, i0, tid, kh_g, kl_g, vh_g, vl_g, z);
    asm volatile("cp.async.commit_group;" ::: "memory");

    float mrow0 = -3.0e38f, mrow1 = -3.0e38f, lrow0 = 0.f, lrow1 = 0.f;
    float accO[8][4];
#pragma unroll
    for (int nt = 0; nt < 8; nt++)
#pragma unroll
        for (int e = 0; e < 4; e++) accO[nt][e] = 0.f;

    for (int jt = 0; jt < 16; jt++) {
        if (jt > 0) __syncthreads();     // all warps done with buffer (jt+1)&1
        if (jt + 1 < 16) {
            attn_load_kvz(sb, (jt + 1) & 1, (jt + 1) * 64, h, i0, tid,
                          kh_g, kl_g, vh_g, vl_g, z);
            asm volatile("cp.async.commit_group;" ::: "memory");
            asm volatile("cp.async.wait_group 1;" ::: "memory");
        } else {
            asm volatile("cp.async.wait_group 0;" ::: "memory");
        }
        __syncthreads();

        uint32_t stg = sb + ASTG + (uint32_t)(jt & 1) * SSZ;

        // ---- QK: S = Q @ K^T (3-term) ----
        float accS[8][4];
#pragma unroll
        for (int nt = 0; nt < 8; nt++)
#pragma unroll
            for (int e = 0; e < 4; e++) accS[nt][e] = 0.f;

#pragma unroll
        for (int kk = 0; kk < 4; kk++) {
            uint32_t qh4[4], ql4[4];
            uint32_t offq = swz((uint32_t)((r0 + (ln & 15)) * 128
                                           + kk * 32 + (ln >> 4) * 16));
            ldm_x4(qh4, sb + AQ_H + offq);
            ldm_x4(ql4, sb + AQ_L + offq);
#pragma unroll
            for (int np = 0; np < 4; np++) {
                uint32_t offk = swz((uint32_t)((np * 16 + (ln & 7) + ((ln >> 4) & 1) * 8) * 128
                                               + kk * 32 + ((ln >> 3) & 1) * 16));
                uint32_t th[4], tl[4];
                ldm_x4(th, stg + SKH + offk);
                ldm_x4(tl, stg + SKL + offk);
                mma16816(accS[2 * np], qh4, th);
                mma16816(accS[2 * np], ql4, th);
                mma16816(accS[2 * np], qh4, tl);
                mma16816(accS[2 * np + 1], qh4, th + 2);
                mma16816(accS[2 * np + 1], ql4, th + 2);
                mma16816(accS[2 * np + 1], qh4, tl + 2);
            }
        }

        // ---- scale + z, row max (register softmax) ----
        const float* zs = (const float*)(smra + ASTG + (size_t)(jt & 1) * SSZ + SZO);
        const int rA = r0 + er, rB = r0 + er + 8;
        float mx0 = -3.0e38f, mx1 = -3.0e38f;
#pragma unroll
        for (int nt = 0; nt < 8; nt++) {
            float2 z0 = *(const float2*)&zs[rA * 68 + nt * 8 + ec];
            float2 z1 = *(const float2*)&zs[rB * 68 + nt * 8 + ec];
            accS[nt][0] = fmaf(accS[nt][0], 0.125f, z0.x);
            accS[nt][1] = fmaf(accS[nt][1], 0.125f, z0.y);
            accS[nt][2] = fmaf(accS[nt][2], 0.125f, z1.x);
            accS[nt][3] = fmaf(accS[nt][3], 0.125f, z1.y);
            mx0 = fmaxf(mx0, fmaxf(accS[nt][0], accS[nt][1]));
            mx1 = fmaxf(mx1, fmaxf(accS[nt][2], accS[nt][3]));
        }
        mx0 = fmaxf(mx0, __shfl_xor_sync(0xffffffffu, mx0, 1));
        mx0 = fmaxf(mx0, __shfl_xor_sync(0xffffffffu, mx0, 2));
        mx1 = fmaxf(mx1, __shfl_xor_sync(0xffffffffu, mx1, 1));
        mx1 = fmaxf(mx1, __shfl_xor_sync(0xffffffffu, mx1, 2));
        float mn0 = fmaxf(mrow0, mx0), mn1 = fmaxf(mrow1, mx1);
        float sc0 = fexp(mrow0 - mn0), sc1 = fexp(mrow1 - mn1);
        mrow0 = mn0; mrow1 = mn1;

        float sum0 = 0.f, sum1 = 0.f;
#pragma unroll
        for (int nt = 0; nt < 8; nt++) {
            accS[nt][0] = fexp(accS[nt][0] - mn0);
            accS[nt][1] = fexp(accS[nt][1] - mn0);
            accS[nt][2] = fexp(accS[nt][2] - mn1);
            accS[nt][3] = fexp(accS[nt][3] - mn1);
            sum0 += accS[nt][0] + accS[nt][1];
            sum1 += accS[nt][2] + accS[nt][3];
            accO[nt][0] *= sc0; accO[nt][1] *= sc0;
            accO[nt][2] *= sc1; accO[nt][3] *= sc1;
        }
        sum0 += __shfl_xor_sync(0xffffffffu, sum0, 1);
        sum0 += __shfl_xor_sync(0xffffffffu, sum0, 2);
        sum1 += __shfl_xor_sync(0xffffffffu, sum1, 1);
        sum1 += __shfl_xor_sync(0xffffffffu, sum1, 2);
        lrow0 = lrow0 * sc0 + sum0;
        lrow1 = lrow1 * sc1 + sum1;

        // ---- in-register P -> A-frag repack (hi/lo) ----
        uint32_t pah[4][4], pal[4][4];
#pragma unroll
        for (int kk = 0; kk < 4; kk++) {
            pah[kk][0] = pk_hi(accS[2 * kk][0], accS[2 * kk][1]);
            pah[kk][1] = pk_hi(accS[2 * kk][2], accS[2 * kk][3]);
            pah[kk][2] = pk_hi(accS[2 * kk + 1][0], accS[2 * kk + 1][1]);
            pah[kk][3] = pk_hi(accS[2 * kk + 1][2], accS[2 * kk + 1][3]);
            pal[kk][0] = pk_lo(accS[2 * kk][0], accS[2 * kk][1]);
            pal[kk][1] = pk_lo(accS[2 * kk][2], accS[2 * kk][3]);
            pal[kk][2] = pk_lo(accS[2 * kk + 1][0], accS[2 * kk + 1][1]);
            pal[kk][3] = pk_lo(accS[2 * kk + 1][2], accS[2 * kk + 1][3]);
        }

        // ---- PV: O += P @ V (3-term, V via ldmatrix.trans) ----
#pragma unroll
        for (int kk = 0; kk < 4; kk++) {
#pragma unroll
            for (int np = 0; np < 4; np++) {
                uint32_t ov = swz((uint32_t)((kk * 16 + (ln & 7) + ((ln >> 3) & 1) * 8) * 128
                                             + (np * 16 + ((ln >> 4) & 1) * 8) * 2));
                uint32_t th[4], tl[4];
                ldm_x4t(th, stg + SVH + ov);
                ldm_x4t(tl, stg + SVL + ov);
                mma16816(accO[2 * np], pah[kk], th);
                mma16816(accO[2 * np], pal[kk], th);
                mma16816(accO[2 * np], pah[kk], tl);
                mma16816(accO[2 * np + 1], pah[kk], th + 2);
                mma16816(accO[2 * np + 1], pal[kk], th + 2);
                mma16816(accO[2 * np + 1], pah[kk], tl + 2);
            }
        }
    }

    // ---- epilogue: o = accO/l, fused with g (*) . , split to bf16 hi/lo ----
    float inv0 = 1.f / lrow0, inv1 = 1.f / lrow1;
    const int rowA = i0 + r0 + er;
#pragma unroll
    for (int nt = 0; nt < 8; nt++) {
        int col = h * HD + nt * 8 + ec;
        float2 gv0 = *(const float2*)&g[(size_t)rowA * CS + col];
        float2 gv1 = *(const float2*)&g[(size_t)(rowA + 8) * CS + col];
        float x0 = accO[nt][0] * inv0 * gv0.x;
        float x1 = accO[nt][1] * inv0 * gv0.y;
        float x2 = accO[nt][2] * inv1 * gv1.x;
        float x3 = accO[nt][3] * inv1 * gv1.y;
        uint32_t h0 = pk_hi(x0, x1), l0 = pk_lo(x0, x1);
        uint32_t h1 = pk_hi(x2, x3), l1 = pk_lo(x2, x3);
        *(uint32_t*)(goh + (size_t)rowA * CS + col) = h0;
        *(uint32_t*)(gol + (size_t)rowA * CS + col) = l0;
        *(uint32_t*)(goh + (size_t)(rowA + 8) * CS + col) = h1;
        *(uint32_t*)(gol + (size_t)(rowA + 8) * CS + col) = l1;
    }
}

// ---------------- launch ----------------
extern "C" void kernel_launch(void* const* d_in, const int* in_sizes, int n_in,
                              void* d_out, int out_size)
{
    const float* s    = (const float*)d_in[0];
    const float* kin  = (const float*)d_in[1];
    const float* mask = (const float*)d_in[2];
    const float* bias = (const float*)d_in[3];
    const float* Wq   = (const float*)d_in[4];
    const float* bq   = (const float*)d_in[5];
    const float* Wk   = (const float*)d_in[6];
    const float* Wv   = (const float*)d_in[7];
    const float* Wg   = (const float*)d_in[8];
    const float* Wo   = (const float*)d_in[9];
    const float* Wz   = (const float*)d_in[10];
    float* out = (float*)d_out;

    float *g, *z;
    cudaGetSymbolAddress((void**)&g, g_g);
    cudaGetSymbolAddress((void**)&z, g_z);

    __nv_bfloat16 *sh, *sl, *xh, *xl, *wqh, *wql, *wkh, *wkl,
                  *wvh, *wvl, *wgh, *wgl, *woh, *wol, *goh, *gol,
                  *qbh, *qbl, *kbh, *kbl, *vbh, *vbl;
    cudaGetSymbolAddress((void**)&sh,  g_sh);  cudaGetSymbolAddress((void**)&sl,  g_sl);
    cudaGetSymbolAddress((void**)&xh,  g_xh);  cudaGetSymbolAddress((void**)&xl,  g_xl);
    cudaGetSymbolAddress((void**)&wqh, g_wqh); cudaGetSymbolAddress((void**)&wql, g_wql);
    cudaGetSymbolAddress((void**)&wkh, g_wkh); cudaGetSymbolAddress((void**)&wkl, g_wkl);
    cudaGetSymbolAddress((void**)&wvh, g_wvh); cudaGetSymbolAddress((void**)&wvl, g_wvl);
    cudaGetSymbolAddress((void**)&wgh, g_wgh); cudaGetSymbolAddress((void**)&wgl, g_wgl);
    cudaGetSymbolAddress((void**)&woh, g_woh); cudaGetSymbolAddress((void**)&wol, g_wol);
    cudaGetSymbolAddress((void**)&goh, g_goh); cudaGetSymbolAddress((void**)&gol, g_gol);
    cudaGetSymbolAddress((void**)&qbh, g_qbh); cudaGetSymbolAddress((void**)&qbl, g_qbl);
    cudaGetSymbolAddress((void**)&kbh, g_kbh); cudaGetSymbolAddress((void**)&kbl, g_kbl);
    cudaGetSymbolAddress((void**)&vbh, g_vbh); cudaGetSymbolAddress((void**)&vbl, g_vbl);

    // lazy stream/event setup (first call is the uncaptured correctness run)
    static cudaStream_t s2 = nullptr;
    static cudaEvent_t ev1 = nullptr, ev2 = nullptr;
    if (!s2) {
        cudaStreamCreateWithFlags(&s2, cudaStreamNonBlocking);
        cudaEventCreateWithFlags(&ev1, cudaEventDisableTiming);
        cudaEventCreateWithFlags(&ev2, cudaEventDisableTiming);
    }

    // fork: zbias (HBM-bound) runs concurrently on s2
    cudaEventRecord(ev1, 0);
    cudaStreamWaitEvent(s2, ev1, 0);
    cudaFuncSetAttribute(zbias_kernel, cudaFuncAttributeMaxDynamicSharedMemorySize, ZB_SMEM);
    zbias_kernel<<<dim3(NI / 2, NJ / 256), 256, ZB_SMEM, s2>>>(bias, Wz, mask, z);
    cudaEventRecord(ev2, s2);

    // main stream: split + projections (compute-bound)
    SplitArgs sa;
    sa.src[0] = s;   sa.hi[0] = sh;  sa.lo[0] = sl;
    sa.src[1] = kin; sa.hi[1] = xh;  sa.lo[1] = xl;
    sa.src[2] = Wq;  sa.hi[2] = wqh; sa.lo[2] = wql;
    sa.src[3] = Wk;  sa.hi[3] = wkh; sa.lo[3] = wkl;
    sa.src[4] = Wv;  sa.hi[4] = wvh; sa.lo[4] = wvl;
    sa.src[5] = Wg;  sa.hi[5] = wgh; sa.lo[5] = wgl;
    sa.src[6] = Wo;  sa.hi[6] = woh; sa.lo[6] = wol;
    split7<<<dim3(256, 7), 256>>>(sa);

    cudaFuncSetAttribute(gemm_tc4, cudaFuncAttributeMaxDynamicSharedMemorySize, GEMM_SMEM);
    gemm_tc4<<<dim3(8, 8, 4), 256, GEMM_SMEM>>>(
        sh, sl, xh, xl, wqh, wql, wkh, wkl, wvh, wvl, wgh, wgl, bq,
        qbh, qbl, kbh, kbl, vbh, vbl, g);

    // join: attn needs z
    cudaStreamWaitEvent(0, ev2, 0);

    cudaFuncSetAttribute(attn_mma, cudaFuncAttributeMaxDynamicSharedMemorySize, AT_SMEM);
    attn_mma<<<dim3(NH, NI / 128), 256, AT_SMEM>>>(
        qbh, qbl, kbh, kbl, vbh, vbl, z, g, goh, gol);

    cudaFuncSetAttribute(gemm_out64, cudaFuncAttributeMaxDynamicSharedMemorySize, G64_SMEM);
    gemm_out64<<<dim3(CS / 128, NI / 64), 256, G64_SMEM>>>(goh, gol, woh, wol, out);
}

// round 12
// speedup vs baseline: 1.4032x; 1.4032x over previous
#include <cuda_runtime.h>
#include <cuda_bf16.h>
#include <math.h>
#include <stdint.h>

#define CS 1024
#define CZ 128
#define NH 16
#define HD 64
#define NI 1024
#define NJ 1024
#define NELEM (NI * CS)

// ---------------- scratch (device globals; no allocation allowed) ----------------
__device__ float g_g[NELEM];
__device__ float g_z[(size_t)NH * NI * NJ];   // 64 MB

// bf16 hi/lo split buffers (inputs + weights)
__device__ __nv_bfloat16 g_sh[NELEM],  g_sl[NELEM];     // s
__device__ __nv_bfloat16 g_xh[NELEM],  g_xl[NELEM];     // k_in
__device__ __nv_bfloat16 g_wqh[NELEM], g_wql[NELEM];
__device__ __nv_bfloat16 g_wkh[NELEM], g_wkl[NELEM];
__device__ __nv_bfloat16 g_wvh[NELEM], g_wvl[NELEM];
__device__ __nv_bfloat16 g_wgh[NELEM], g_wgl[NELEM];
__device__ __nv_bfloat16 g_woh[NELEM], g_wol[NELEM];
__device__ __nv_bfloat16 g_goh[NELEM], g_gol[NELEM];    // g (*) o  (written by attn epilogue)
// q/k/v hi/lo (written directly by projection epilogue)
__device__ __nv_bfloat16 g_qbh[NELEM], g_qbl[NELEM];
__device__ __nv_bfloat16 g_kbh[NELEM], g_kbl[NELEM];
__device__ __nv_bfloat16 g_vbh[NELEM], g_vbl[NELEM];

// =====================================================================
// helpers (baseline PTX only — NO tcgen05 on this toolchain path)
// =====================================================================
__device__ __forceinline__ uint32_t smem_u32(const void* p) {
    uint32_t a;
    asm("{ .reg .u64 t; cvta.to.shared.u64 t, %1; cvt.u32.u64 %0, t; }"
        : "=r"(a) : "l"(p));
    return a;
}

__device__ __forceinline__ void cp16(uint32_t dst, const void* src) {
    uint64_t g;
    asm("cvta.to.global.u64 %0, %1;" : "=l"(g) : "l"(src));
    asm volatile("cp.async.cg.shared.global [%0], [%1], 16;" :: "r"(dst), "l"(g));
}

__device__ __forceinline__ void ldm_x4(uint32_t* r, uint32_t addr) {
    asm volatile("ldmatrix.sync.aligned.m8n8.x4.shared.b16 {%0,%1,%2,%3}, [%4];"
        : "=r"(r[0]), "=r"(r[1]), "=r"(r[2]), "=r"(r[3]) : "r"(addr));
}

__device__ __forceinline__ void ldm_x4t(uint32_t* r, uint32_t addr) {
    asm volatile("ldmatrix.sync.aligned.m8n8.x4.trans.shared.b16 {%0,%1,%2,%3}, [%4];"
        : "=r"(r[0]), "=r"(r[1]), "=r"(r[2]), "=r"(r[3]) : "r"(addr));
}

__device__ __forceinline__ void mma16816(float* d, const uint32_t* a, const uint32_t* b) {
    asm volatile(
        "mma.sync.aligned.m16n8k16.row.col.f32.bf16.bf16.f32 "
        "{%0,%1,%2,%3}, {%4,%5,%6,%7}, {%8,%9}, {%0,%1,%2,%3};"
        : "+f"(d[0]), "+f"(d[1]), "+f"(d[2]), "+f"(d[3])
        : "r"(a[0]), "r"(a[1]), "r"(a[2]), "r"(a[3]), "r"(b[0]), "r"(b[1]));
}

__device__ __forceinline__ uint32_t swz(uint32_t off) {
    return off ^ ((off >> 3) & 0x70);
}

// FMA-pipe exp (no MUFU): exp(x) = 2^(x*log2e), poly on [-0.5,0.5]
__device__ __forceinline__ float fexp(float x) {
    float t = fmaxf(x * 1.4426950408889634f, -126.0f);
    float zz = t + 12582912.0f;              // 1.5 * 2^23 magic round
    int   ii = __float_as_int(zz) - 0x4B400000;
    float f  = t - (zz - 12582912.0f);
    float p  = 1.3333558146e-3f;
    p = fmaf(p, f, 9.6181291076e-3f);
    p = fmaf(p, f, 5.5504108664e-2f);
    p = fmaf(p, f, 2.4022650696e-1f);
    p = fmaf(p, f, 6.9314718056e-1f);
    p = fmaf(p, f, 1.0f);
    return __int_as_float(__float_as_int(p) + (ii << 23));
}

__device__ __forceinline__ uint32_t pk_hi(float a, float b) {
    __nv_bfloat162 t;
    t.x = __float2bfloat16(a); t.y = __float2bfloat16(b);
    return *(uint32_t*)&t;
}
__device__ __forceinline__ uint32_t pk_lo(float a, float b) {
    __nv_bfloat16 ha = __float2bfloat16(a), hb = __float2bfloat16(b);
    __nv_bfloat162 t;
    t.x = __float2bfloat16(a - __bfloat162float(ha));
    t.y = __float2bfloat16(b - __bfloat162float(hb));
    return *(uint32_t*)&t;
}

// =====================================================================
// split conversion: x -> (hi=bf16(x), lo=bf16(x-hi))
// =====================================================================
struct SplitArgs {
    const float* src[7];
    __nv_bfloat16* hi[7];
    __nv_bfloat16* lo[7];
};

__device__ __forceinline__ void split4(float4 v, __nv_bfloat162* hi2,
                                       __nv_bfloat162* lo2, size_t i) {
    __nv_bfloat16 h0 = __float2bfloat16(v.x);
    __nv_bfloat16 h1 = __float2bfloat16(v.y);
    __nv_bfloat16 h2 = __float2bfloat16(v.z);
    __nv_bfloat16 h3 = __float2bfloat16(v.w);
    __nv_bfloat16 l0 = __float2bfloat16(v.x - __bfloat162float(h0));
    __nv_bfloat16 l1 = __float2bfloat16(v.y - __bfloat162float(h1));
    __nv_bfloat16 l2 = __float2bfloat16(v.z - __bfloat162float(h2));
    __nv_bfloat16 l3 = __float2bfloat16(v.w - __bfloat162float(h3));
    __nv_bfloat162 ph0; ph0.x = h0; ph0.y = h1;
    __nv_bfloat162 ph1; ph1.x = h2; ph1.y = h3;
    __nv_bfloat162 pl0; pl0.x = l0; pl0.y = l1;
    __nv_bfloat162 pl1; pl1.x = l2; pl1.y = l3;
    hi2[2 * i] = ph0; hi2[2 * i + 1] = ph1;
    lo2[2 * i] = pl0; lo2[2 * i + 1] = pl1;
}

__global__ __launch_bounds__(256) void split7(SplitArgs a) {
    const float4* src = (const float4*)a.src[blockIdx.y];
    __nv_bfloat162* hi2 = (__nv_bfloat162*)a.hi[blockIdx.y];
    __nv_bfloat162* lo2 = (__nv_bfloat162*)a.lo[blockIdx.y];
    int t = blockIdx.x * 256 + threadIdx.x;
    for (size_t i = t; i < NELEM / 4; i += 256 * 256)
        split4(src[i], hi2, lo2, i);
}

// =====================================================================
// bf16-split GEMM via mma.sync: 128x128 tiles (projections)
// =====================================================================
#define STAGE_BYTES 65536
#define GEMM_SMEM (3 * STAGE_BYTES + 1024)

__device__ __forceinline__ void load_stage(
    uint32_t sbase, int s, int tid,
    const __nv_bfloat16* Ah, const __nv_bfloat16* Al,
    const __nv_bfloat16* Bh, const __nv_bfloat16* Bl,
    int m0, int n0)
{
    uint32_t sb = sbase + (uint32_t)(s % 3) * STAGE_BYTES;
    int k0 = s * 64;
#pragma unroll
    for (int p = 0; p < 4; p++) {
        int slot = tid + 256 * p;
        int row = slot >> 3;
        int ch = slot & 7;
        uint32_t off = swz((uint32_t)(row * 128 + ch * 16));
        size_t aoff = (size_t)(m0 + row) * CS + k0 + ch * 8;
        size_t boff = (size_t)(n0 + row) * CS + k0 + ch * 8;
        cp16(sb + off,          Ah + aoff);
        cp16(sb + 16384u + off, Al + aoff);
        cp16(sb + 32768u + off, Bh + boff);
        cp16(sb + 49152u + off, Bl + boff);
    }
}

template <int MODE, int OUT>   // MODE: 0 plain,1 +bias,2 sigmoid; OUT: 0 fp32, 1 bf16 hi/lo
__device__ void gemm_mma_core(
    const __nv_bfloat16* Ah, const __nv_bfloat16* Al,
    const __nv_bfloat16* Bh, const __nv_bfloat16* Bl,
    const float* bvec, float* C,
    __nv_bfloat16* Ch, __nv_bfloat16* Cl, int m0, int n0)
{
    extern __shared__ __align__(16) char dsm[];
    const int tid = threadIdx.x;
    uint32_t sbase = smem_u32(dsm);
    sbase = (sbase + 1023u) & ~1023u;

    const int w  = tid >> 5;
    const int ln = tid & 31;
    const int wm = w & 3;
    const int wn = w >> 2;

    float acc[2][8][4];
#pragma unroll
    for (int mt = 0; mt < 2; mt++)
#pragma unroll
        for (int nt = 0; nt < 8; nt++)
#pragma unroll
            for (int e = 0; e < 4; e++) acc[mt][nt][e] = 0.f;

    load_stage(sbase, 0, tid, Ah, Al, Bh, Bl, m0, n0);
    asm volatile("cp.async.commit_group;" ::: "memory");
    load_stage(sbase, 1, tid, Ah, Al, Bh, Bl, m0, n0);
    asm volatile("cp.async.commit_group;" ::: "memory");

    const int a_row = wm * 32 + (ln & 15);
    const int a_kb  = (ln >> 4) * 16;
    const int b_row = wn * 64 + (ln & 7) + ((ln >> 4) & 1) * 8;
    const int b_kb  = ((ln >> 3) & 1) * 16;

    for (int s = 0; s < 16; s++) {
        if (s < 15) asm volatile("cp.async.wait_group 1;" ::: "memory");
        else        asm volatile("cp.async.wait_group 0;" ::: "memory");
        __syncthreads();

        uint32_t sb = sbase + (uint32_t)(s % 3) * STAGE_BYTES;
#pragma unroll
        for (int kk = 0; kk < 4; kk++) {
            uint32_t ah[2][4], al[2][4], bh[8][2], bl[8][2];
#pragma unroll
            for (int mt = 0; mt < 2; mt++) {
                uint32_t off = swz((uint32_t)((a_row + mt * 16) * 128 + kk * 32 + a_kb));
                ldm_x4(ah[mt], sb + off);
                ldm_x4(al[mt], sb + 16384u + off);
            }
#pragma unroll
            for (int np = 0; np < 4; np++) {
                uint32_t off = swz((uint32_t)((b_row + np * 16) * 128 + kk * 32 + b_kb));
                uint32_t t4[4];
                ldm_x4(t4, sb + 32768u + off);
                bh[2 * np][0] = t4[0]; bh[2 * np][1] = t4[1];
                bh[2 * np + 1][0] = t4[2]; bh[2 * np + 1][1] = t4[3];
                ldm_x4(t4, sb + 49152u + off);
                bl[2 * np][0] = t4[0]; bl[2 * np][1] = t4[1];
                bl[2 * np + 1][0] = t4[2]; bl[2 * np + 1][1] = t4[3];
            }
#pragma unroll
            for (int mt = 0; mt < 2; mt++)
#pragma unroll
                for (int nt = 0; nt < 8; nt++) {
                    mma16816(acc[mt][nt], ah[mt], bh[nt]);
                    mma16816(acc[mt][nt], al[mt], bh[nt]);
                    mma16816(acc[mt][nt], ah[mt], bl[nt]);
                }
        }

        if (s + 2 < 16) {
            load_stage(sbase, s + 2, tid, Ah, Al, Bh, Bl, m0, n0);
            asm volatile("cp.async.commit_group;" ::: "memory");
        }
    }

    const int er = ln >> 2;
    const int ec = (ln & 3) * 2;
#pragma unroll
    for (int mt = 0; mt < 2; mt++) {
#pragma unroll
        for (int nt = 0; nt < 8; nt++) {
            int m = m0 + wm * 32 + mt * 16 + er;
            int n = n0 + wn * 64 + nt * 8 + ec;
#pragma unroll
            for (int half = 0; half < 2; half++) {
                float2 r;
                r.x = acc[mt][nt][2 * half + 0];
                r.y = acc[mt][nt][2 * half + 1];
                if (MODE == 1) { r.x += bvec[n]; r.y += bvec[n + 1]; }
                else if (MODE == 2) {
                    r.x = 1.f / (1.f + __expf(-r.x));
                    r.y = 1.f / (1.f + __expf(-r.y));
                }
                size_t idx = (size_t)(m + half * 8) * CS + n;
                if (OUT == 0) {
                    *(float2*)(C + idx) = r;
                } else {
                    __nv_bfloat162 hh, ll;
                    uint32_t uh = pk_hi(r.x, r.y), ul = pk_lo(r.x, r.y);
                    hh = *(__nv_bfloat162*)&uh; ll = *(__nv_bfloat162*)&ul;
                    *(__nv_bfloat162*)(Ch + idx) = hh;
                    *(__nv_bfloat162*)(Cl + idx) = ll;
                }
            }
        }
    }
}

__global__ __launch_bounds__(256, 1) void gemm_tc4(
    const __nv_bfloat16* sh,  const __nv_bfloat16* sl,
    const __nv_bfloat16* xh,  const __nv_bfloat16* xl,
    const __nv_bfloat16* wqh, const __nv_bfloat16* wql,
    const __nv_bfloat16* wkh, const __nv_bfloat16* wkl,
    const __nv_bfloat16* wvh, const __nv_bfloat16* wvl,
    const __nv_bfloat16* wgh, const __nv_bfloat16* wgl,
    const float* bq,
    __nv_bfloat16* qbh, __nv_bfloat16* qbl,
    __nv_bfloat16* kbh, __nv_bfloat16* kbl,
    __nv_bfloat16* vbh, __nv_bfloat16* vbl,
    float* g)
{
    int m0 = blockIdx.y * 128, n0 = blockIdx.x * 128;
    switch (blockIdx.z) {
        case 0:  gemm_mma_core<1, 1>(sh, sl, wqh, wql, bq, nullptr, qbh, qbl, m0, n0); break;
        case 1:  gemm_mma_core<0, 1>(xh, xl, wkh, wkl, nullptr, nullptr, kbh, kbl, m0, n0); break;
        case 2:  gemm_mma_core<0, 1>(xh, xl, wvh, wvl, nullptr, nullptr, vbh, vbl, m0, n0); break;
        default: gemm_mma_core<2, 0>(sh, sl, wgh, wgl, nullptr, g, nullptr, nullptr, m0, n0); break;
    }
}

// =====================================================================
// Output GEMM: BM=64 x BN=128 tiles -> 128 CTAs (one full wave)
// =====================================================================
#define G64_SSZ 49152
#define G64_SMEM (3 * G64_SSZ + 1024)

__device__ __forceinline__ void load_stage64(
    uint32_t sbase, int s, int tid,
    const __nv_bfloat16* Ah, const __nv_bfloat16* Al,
    const __nv_bfloat16* Bh, const __nv_bfloat16* Bl,
    int m0, int n0)
{
    uint32_t sb = sbase + (uint32_t)(s % 3) * G64_SSZ;
    int k0 = s * 64;
#pragma unroll
    for (int p = 0; p < 4; p++) {          // A hi/lo: 64 rows x 8 x 2
        int slot = tid + 256 * p;
        int arr = slot >> 9, idx = slot & 511;
        int row = idx >> 3, ch = idx & 7;
        cp16(sb + (uint32_t)arr * 8192u + swz((uint32_t)(row * 128 + ch * 16)),
             (arr ? Al : Ah) + (size_t)(m0 + row) * CS + k0 + ch * 8);
    }
#pragma unroll
    for (int p = 0; p < 8; p++) {          // B hi/lo: 128 rows x 8 x 2
        int slot = tid + 256 * p;
        int arr = slot >> 10, idx = slot & 1023;
        int row = idx >> 3, ch = idx & 7;
        cp16(sb + 16384u + (uint32_t)arr * 16384u + swz((uint32_t)(row * 128 + ch * 16)),
             (arr ? Bl : Bh) + (size_t)(n0 + row) * CS + k0 + ch * 8);
    }
}

__global__ __launch_bounds__(256, 1) void gemm_out64(
    const __nv_bfloat16* Ah, const __nv_bfloat16* Al,
    const __nv_bfloat16* Bh, const __nv_bfloat16* Bl,
    float* out)
{
    extern __shared__ __align__(16) char dsm[];
    const int tid = threadIdx.x;
    uint32_t sbase = smem_u32(dsm);
    sbase = (sbase + 1023u) & ~1023u;
    const int m0 = blockIdx.y * 64, n0 = blockIdx.x * 128;

    const int w = tid >> 5, ln = tid & 31;
    const int wm = w & 1;        // 2 warps over M (32 rows)
    const int wn = w >> 1;       // 4 warps over N (32 cols)

    float acc[2][4][4];
#pragma unroll
    for (int mt = 0; mt < 2; mt++)
#pragma unroll
        for (int nt = 0; nt < 4; nt++)
#pragma unroll
            for (int e = 0; e < 4; e++) acc[mt][nt][e] = 0.f;

    load_stage64(sbase, 0, tid, Ah, Al, Bh, Bl, m0, n0);
    asm volatile("cp.async.commit_group;" ::: "memory");
    load_stage64(sbase, 1, tid, Ah, Al, Bh, Bl, m0, n0);
    asm volatile("cp.async.commit_group;" ::: "memory");

    const int a_row = wm * 32 + (ln & 15);
    const int a_kb  = (ln >> 4) * 16;
    const int b_row = wn * 32 + (ln & 7) + ((ln >> 4) & 1) * 8;
    const int b_kb  = ((ln >> 3) & 1) * 16;

    for (int s = 0; s < 16; s++) {
        if (s < 15) asm volatile("cp.async.wait_group 1;" ::: "memory");
        else        asm volatile("cp.async.wait_group 0;" ::: "memory");
        __syncthreads();

        uint32_t sb = sbase + (uint32_t)(s % 3) * G64_SSZ;
#pragma unroll
        for (int kk = 0; kk < 4; kk++) {
            uint32_t ah4[2][4], al4[2][4], bh[4][2], bl[4][2];
#pragma unroll
            for (int mt = 0; mt < 2; mt++) {
                uint32_t off = swz((uint32_t)((a_row + mt * 16) * 128 + kk * 32 + a_kb));
                ldm_x4(ah4[mt], sb + off);
                ldm_x4(al4[mt], sb + 8192u + off);
            }
#pragma unroll
            for (int np = 0; np < 2; np++) {
                uint32_t off = swz((uint32_t)((b_row + np * 16) * 128 + kk * 32 + b_kb));
                uint32_t t4[4];
                ldm_x4(t4, sb + 16384u + off);
                bh[2 * np][0] = t4[0]; bh[2 * np][1] = t4[1];
                bh[2 * np + 1][0] = t4[2]; bh[2 * np + 1][1] = t4[3];
                ldm_x4(t4, sb + 32768u + off);
                bl[2 * np][0] = t4[0]; bl[2 * np][1] = t4[1];
                bl[2 * np + 1][0] = t4[2]; bl[2 * np + 1][1] = t4[3];
            }
#pragma unroll
            for (int mt = 0; mt < 2; mt++)
#pragma unroll
                for (int nt = 0; nt < 4; nt++) {
                    mma16816(acc[mt][nt], ah4[mt], bh[nt]);
                    mma16816(acc[mt][nt], al4[mt], bh[nt]);
                    mma16816(acc[mt][nt], ah4[mt], bl[nt]);
                }
        }

        if (s + 2 < 16) {
            load_stage64(sbase, s + 2, tid, Ah, Al, Bh, Bl, m0, n0);
            asm volatile("cp.async.commit_group;" ::: "memory");
        }
    }

    const int er = ln >> 2, ec = (ln & 3) * 2;
#pragma unroll
    for (int mt = 0; mt < 2; mt++)
#pragma unroll
        for (int nt = 0; nt < 4; nt++) {
            int m = m0 + wm * 32 + mt * 16 + er;
            int n = n0 + wn * 32 + nt * 8 + ec;
            float2 r0; r0.x = acc[mt][nt][0]; r0.y = acc[mt][nt][1];
            float2 r1; r1.x = acc[mt][nt][2]; r1.y = acc[mt][nt][3];
            *(float2*)(out + (size_t)m * CS + n) = r0;
            *(float2*)(out + (size_t)(m + 8) * CS + n) = r1;
        }
}

// ---------------- z kernel ----------------
#define ZB_SMEM ((2 * 256 * 33 + CZ * NH) * 4)
__global__ __launch_bounds__(256) void zbias_kernel(
    const float* __restrict__ bias, const float* __restrict__ Wz,
    const float* __restrict__ mask, float* __restrict__ z)
{
    extern __shared__ float sm[];
    float* bs = sm;
    float* wzs = sm + 2 * 256 * 33;

    const int tid = threadIdx.x;
    const int jg = tid & 31;
    const int hg = (tid >> 5) & 3;
    const int ig = tid >> 7;
    const int i0 = blockIdx.x * 2;
    const int j0 = blockIdx.y * 256;

    for (int t = tid; t < CZ * NH; t += 256) wzs[t] = Wz[t];

    float acc[8][4];
#pragma unroll
    for (int kk = 0; kk < 8; kk++)
#pragma unroll
        for (int hh = 0; hh < 4; hh++) acc[kk][hh] = 0.f;

    for (int cc = 0; cc < CZ; cc += 32) {
        __syncthreads();
#pragma unroll
        for (int p = 0; p < 16; p++) {
            int slot = tid + 256 * p;
            int c4 = slot & 7;
            int row = slot >> 3;
            int ii = row >> 8;
            int j = row & 255;
            float4 vv = *(const float4*)(bias +
                ((size_t)(i0 + ii) * NJ + (j0 + j)) * CZ + cc + c4 * 4);
            float* dst = bs + ((size_t)ii * 256 + j) * 33 + c4 * 4;
            dst[0] = vv.x; dst[1] = vv.y; dst[2] = vv.z; dst[3] = vv.w;
        }
        __syncthreads();

#pragma unroll
        for (int c = 0; c < 32; c++) {
            const float* wrow = wzs + (cc + c) * NH + hg * 4;
            float w0 = wrow[0], w1 = wrow[1], w2 = wrow[2], w3 = wrow[3];
#pragma unroll
            for (int kk = 0; kk < 8; kk++) {
                float bv = bs[((size_t)ig * 256 + (jg + 32 * kk)) * 33 + c];
                acc[kk][0] += bv * w0;
                acc[kk][1] += bv * w1;
                acc[kk][2] += bv * w2;
                acc[kk][3] += bv * w3;
            }
        }
    }

    const int i = i0 + ig;
#pragma unroll
    for (int hh = 0; hh < 4; hh++) {
        int h = hg * 4 + hh;
        size_t base = ((size_t)h * NI + i) * NJ;
#pragma unroll
        for (int kk = 0; kk < 8; kk++) {
            int j = j0 + jg + 32 * kk;
            z[base + j] = acc[kk][hh] + (1.f - mask[j]) * (-1000000.0f);
        }
    }
}

// =====================================================================
// Flash attention v3: CTA = (head, 64 i-rows), 128 threads (4 warps),
// 2 CTAs/SM (80KB smem, 256 thr/SM). z read directly from GMEM.
// Register softmax, in-register P->A-frag repack, double-buffered K/V.
// =====================================================================
#define AQ_H 0
#define AQ_L 8192
#define ASTG 16384
#define SKH 0
#define SKL 8192
#define SVH 16384
#define SVL 24576
#define SSZ 32768
#define AT_SMEM (ASTG + 2 * SSZ)     /* 81920 */

__device__ __forceinline__ void attn_load_kv(
    uint32_t sb, int stage, int j0, int h, int tid,
    const __nv_bfloat16* kh, const __nv_bfloat16* kl,
    const __nv_bfloat16* vh, const __nv_bfloat16* vl)
{
    uint32_t stg = sb + ASTG + (uint32_t)stage * SSZ;
#pragma unroll
    for (int p = 0; p < 16; p++) {
        int slot = tid + 128 * p;
        int arr = slot >> 9, idx = slot & 511;
        int row = idx >> 3, ch = idx & 7;
        const __nv_bfloat16* base =
            (arr == 0) ? kh : (arr == 1) ? kl : (arr == 2) ? vh : vl;
        cp16(stg + (uint32_t)arr * 8192u + swz((uint32_t)(row * 128 + ch * 16)),
             base + (size_t)(j0 + row) * CS + h * HD + ch * 8);
    }
}

__global__ __launch_bounds__(128, 2) void attn_mma(
    const __nv_bfloat16* __restrict__ qh_g, const __nv_bfloat16* __restrict__ ql_g,
    const __nv_bfloat16* __restrict__ kh_g, const __nv_bfloat16* __restrict__ kl_g,
    const __nv_bfloat16* __restrict__ vh_g, const __nv_bfloat16* __restrict__ vl_g,
    const float* __restrict__ z, const float* __restrict__ g,
    __nv_bfloat16* __restrict__ goh, __nv_bfloat16* __restrict__ gol)
{
    extern __shared__ __align__(16) char smra[];
    uint32_t sb = smem_u32(smra);
    const int h = blockIdx.x;
    const int i0 = blockIdx.y * 64;
    const int tid = threadIdx.x;
    const int w = tid >> 5, ln = tid & 31;
    const int r0 = w * 16;               // warp's 16 rows (4 warps x 16 = 64)
    const int er = ln >> 2, ec = (ln & 3) * 2;

    // Q hi/lo (64 x 64 bf16 each): 1024 chunks / 128 threads = 8 per thread
#pragma unroll
    for (int p = 0; p < 8; p++) {
        int slot = tid + 128 * p;
        int arr = slot >> 9, idx = slot & 511;
        int row = idx >> 3, ch = idx & 7;
        cp16(sb + (arr ? AQ_L : AQ_H) + swz((uint32_t)(row * 128 + ch * 16)),
             (arr ? ql_g : qh_g) + (size_t)(i0 + row) * CS + h * HD + ch * 8);
    }
    attn_load_kv(sb, 0, 0, h, tid, kh_g, kl_g, vh_g, vl_g);
    asm volatile("cp.async.commit_group;" ::: "memory");

    // row pointers for direct z loads (rows rA, rB of this thread)
    const float* zA = z + ((size_t)h * NI + i0 + r0 + er) * NJ + ec;
    const float* zB = zA + (size_t)8 * NJ;

    float mrow0 = -3.0e38f, mrow1 = -3.0e38f, lrow0 = 0.f, lrow1 = 0.f;
    float accO[8][4];
#pragma unroll
    for (int nt = 0; nt < 8; nt++)
#pragma unroll
        for (int e = 0; e < 4; e++) accO[nt][e] = 0.f;

    for (int jt = 0; jt < 16; jt++) {
        const int j0 = jt * 64;
        if (jt > 0) __syncthreads();     // all warps done with buffer (jt+1)&1
        if (jt + 1 < 16) {
            attn_load_kv(sb, (jt + 1) & 1, (jt + 1) * 64, h, tid,
                         kh_g, kl_g, vh_g, vl_g);
            asm volatile("cp.async.commit_group;" ::: "memory");
            asm volatile("cp.async.wait_group 1;" ::: "memory");
        } else {
            asm volatile("cp.async.wait_group 0;" ::: "memory");
        }
        __syncthreads();

        // issue z loads early (independent; latency hidden under QK MMAs)
        float2 zr0[8], zr1[8];
#pragma unroll
        for (int nt = 0; nt < 8; nt++) {
            zr0[nt] = *(const float2*)&zA[j0 + nt * 8];
            zr1[nt] = *(const float2*)&zB[j0 + nt * 8];
        }

        uint32_t stg = sb + ASTG + (uint32_t)(jt & 1) * SSZ;

        // ---- QK: S = Q @ K^T (3-term) ----
        float accS[8][4];
#pragma unroll
        for (int nt = 0; nt < 8; nt++)
#pragma unroll
            for (int e = 0; e < 4; e++) accS[nt][e] = 0.f;

#pragma unroll
        for (int kk = 0; kk < 4; kk++) {
            uint32_t qh4[4], ql4[4];
            uint32_t offq = swz((uint32_t)((r0 + (ln & 15)) * 128
                                           + kk * 32 + (ln >> 4) * 16));
            ldm_x4(qh4, sb + AQ_H + offq);
            ldm_x4(ql4, sb + AQ_L + offq);
#pragma unroll
            for (int np = 0; np < 4; np++) {
                uint32_t offk = swz((uint32_t)((np * 16 + (ln & 7) + ((ln >> 4) & 1) * 8) * 128
                                               + kk * 32 + ((ln >> 3) & 1) * 16));
                uint32_t th[4], tl[4];
                ldm_x4(th, stg + SKH + offk);
                ldm_x4(tl, stg + SKL + offk);
                mma16816(accS[2 * np], qh4, th);
                mma16816(accS[2 * np], ql4, th);
                mma16816(accS[2 * np], qh4, tl);
                mma16816(accS[2 * np + 1], qh4, th + 2);
                mma16816(accS[2 * np + 1], ql4, th + 2);
                mma16816(accS[2 * np + 1], qh4, tl + 2);
            }
        }

        // ---- scale + z, row max (register softmax) ----
        float mx0 = -3.0e38f, mx1 = -3.0e38f;
#pragma unroll
        for (int nt = 0; nt < 8; nt++) {
            accS[nt][0] = fmaf(accS[nt][0], 0.125f, zr0[nt].x);
            accS[nt][1] = fmaf(accS[nt][1], 0.125f, zr0[nt].y);
            accS[nt][2] = fmaf(accS[nt][2], 0.125f, zr1[nt].x);
            accS[nt][3] = fmaf(accS[nt][3], 0.125f, zr1[nt].y);
            mx0 = fmaxf(mx0, fmaxf(accS[nt][0], accS[nt][1]));
            mx1 = fmaxf(mx1, fmaxf(accS[nt][2], accS[nt][3]));
        }
        mx0 = fmaxf(mx0, __shfl_xor_sync(0xffffffffu, mx0, 1));
        mx0 = fmaxf(mx0, __shfl_xor_sync(0xffffffffu, mx0, 2));
        mx1 = fmaxf(mx1, __shfl_xor_sync(0xffffffffu, mx1, 1));
        mx1 = fmaxf(mx1, __shfl_xor_sync(0xffffffffu, mx1, 2));
        float mn0 = fmaxf(mrow0, mx0), mn1 = fmaxf(mrow1, mx1);
        float sc0 = fexp(mrow0 - mn0), sc1 = fexp(mrow1 - mn1);
        mrow0 = mn0; mrow1 = mn1;

        float sum0 = 0.f, sum1 = 0.f;
#pragma unroll
        for (int nt = 0; nt < 8; nt++) {
            accS[nt][0] = fexp(accS[nt][0] - mn0);
            accS[nt][1] = fexp(accS[nt][1] - mn0);
            accS[nt][2] = fexp(accS[nt][2] - mn1);
            accS[nt][3] = fexp(accS[nt][3] - mn1);
            sum0 += accS[nt][0] + accS[nt][1];
            sum1 += accS[nt][2] + accS[nt][3];
            accO[nt][0] *= sc0; accO[nt][1] *= sc0;
            accO[nt][2] *= sc1; accO[nt][3] *= sc1;
        }
        sum0 += __shfl_xor_sync(0xffffffffu, sum0, 1);
        sum0 += __shfl_xor_sync(0xffffffffu, sum0, 2);
        sum1 += __shfl_xor_sync(0xffffffffu, sum1, 1);
        sum1 += __shfl_xor_sync(0xffffffffu, sum1, 2);
        lrow0 = lrow0 * sc0 + sum0;
        lrow1 = lrow1 * sc1 + sum1;

        // ---- in-register P -> A-frag repack (hi/lo) ----
        uint32_t pah[4][4], pal[4][4];
#pragma unroll
        for (int kk = 0; kk < 4; kk++) {
            pah[kk][0] = pk_hi(accS[2 * kk][0], accS[2 * kk][1]);
            pah[kk][1] = pk_hi(accS[2 * kk][2], accS[2 * kk][3]);
            pah[kk][2] = pk_hi(accS[2 * kk + 1][0], accS[2 * kk + 1][1]);
            pah[kk][3] = pk_hi(accS[2 * kk + 1][2], accS[2 * kk + 1][3]);
            pal[kk][0] = pk_lo(accS[2 * kk][0], accS[2 * kk][1]);
            pal[kk][1] = pk_lo(accS[2 * kk][2], accS[2 * kk][3]);
            pal[kk][2] = pk_lo(accS[2 * kk + 1][0], accS[2 * kk + 1][1]);
            pal[kk][3] = pk_lo(accS[2 * kk + 1][2], accS[2 * kk + 1][3]);
        }

        // ---- PV: O += P @ V (3-term, V via ldmatrix.trans) ----
#pragma unroll
        for (int kk = 0; kk < 4; kk++) {
#pragma unroll
            for (int np = 0; np < 4; np++) {
                uint32_t ov = swz((uint32_t)((kk * 16 + (ln & 7) + ((ln >> 3) & 1) * 8) * 128
                                             + (np * 16 + ((ln >> 4) & 1) * 8) * 2));
                uint32_t th[4], tl[4];
                ldm_x4t(th, stg + SVH + ov);
                ldm_x4t(tl, stg + SVL + ov);
                mma16816(accO[2 * np], pah[kk], th);
                mma16816(accO[2 * np], pal[kk], th);
                mma16816(accO[2 * np], pah[kk], tl);
                mma16816(accO[2 * np + 1], pah[kk], th + 2);
                mma16816(accO[2 * np + 1], pal[kk], th + 2);
                mma16816(accO[2 * np + 1], pah[kk], tl + 2);
            }
        }
    }

    // ---- epilogue: o = accO/l, fused with g (*) . , split to bf16 hi/lo ----
    float inv0 = 1.f / lrow0, inv1 = 1.f / lrow1;
    const int rowA = i0 + r0 + er;
#pragma unroll
    for (int nt = 0; nt < 8; nt++) {
        int col = h * HD + nt * 8 + ec;
        float2 gv0 = *(const float2*)&g[(size_t)rowA * CS + col];
        float2 gv1 = *(const float2*)&g[(size_t)(rowA + 8) * CS + col];
        float x0 = accO[nt][0] * inv0 * gv0.x;
        float x1 = accO[nt][1] * inv0 * gv0.y;
        float x2 = accO[nt][2] * inv1 * gv1.x;
        float x3 = accO[nt][3] * inv1 * gv1.y;
        uint32_t h0 = pk_hi(x0, x1), l0 = pk_lo(x0, x1);
        uint32_t h1 = pk_hi(x2, x3), l1 = pk_lo(x2, x3);
        *(uint32_t*)(goh + (size_t)rowA * CS + col) = h0;
        *(uint32_t*)(gol + (size_t)rowA * CS + col) = l0;
        *(uint32_t*)(goh + (size_t)(rowA + 8) * CS + col) = h1;
        *(uint32_t*)(gol + (size_t)(rowA + 8) * CS + col) = l1;
    }
}

// ---------------- launch (serial, single stream) ----------------
extern "C" void kernel_launch(void* const* d_in, const int* in_sizes, int n_in,
                              void* d_out, int out_size)
{
    const float* s    = (const float*)d_in[0];
    const float* kin  = (const float*)d_in[1];
    const float* mask = (const float*)d_in[2];
    const float* bias = (const float*)d_in[3];
    const float* Wq   = (const float*)d_in[4];
    const float* bq   = (const float*)d_in[5];
    const float* Wk   = (const float*)d_in[6];
    const float* Wv   = (const float*)d_in[7];
    const float* Wg   = (const float*)d_in[8];
    const float* Wo   = (const float*)d_in[9];
    const float* Wz   = (const float*)d_in[10];
    float* out = (float*)d_out;

    float *g, *z;
    cudaGetSymbolAddress((void**)&g, g_g);
    cudaGetSymbolAddress((void**)&z, g_z);

    __nv_bfloat16 *sh, *sl, *xh, *xl, *wqh, *wql, *wkh, *wkl,
                  *wvh, *wvl, *wgh, *wgl, *woh, *wol, *goh, *gol,
                  *qbh, *qbl, *kbh, *kbl, *vbh, *vbl;
    cudaGetSymbolAddress((void**)&sh,  g_sh);  cudaGetSymbolAddress((void**)&sl,  g_sl);
    cudaGetSymbolAddress((void**)&xh,  g_xh);  cudaGetSymbolAddress((void**)&xl,  g_xl);
    cudaGetSymbolAddress((void**)&wqh, g_wqh); cudaGetSymbolAddress((void**)&wql, g_wql);
    cudaGetSymbolAddress((void**)&wkh, g_wkh); cudaGetSymbolAddress((void**)&wkl, g_wkl);
    cudaGetSymbolAddress((void**)&wvh, g_wvh); cudaGetSymbolAddress((void**)&wvl, g_wvl);
    cudaGetSymbolAddress((void**)&wgh, g_wgh); cudaGetSymbolAddress((void**)&wgl, g_wgl);
    cudaGetSymbolAddress((void**)&woh, g_woh); cudaGetSymbolAddress((void**)&wol, g_wol);
    cudaGetSymbolAddress((void**)&goh, g_goh); cudaGetSymbolAddress((void**)&gol, g_gol);
    cudaGetSymbolAddress((void**)&qbh, g_qbh); cudaGetSymbolAddress((void**)&qbl, g_qbl);
    cudaGetSymbolAddress((void**)&kbh, g_kbh); cudaGetSymbolAddress((void**)&kbl, g_kbl);
    cudaGetSymbolAddress((void**)&vbh, g_vbh); cudaGetSymbolAddress((void**)&vbl, g_vbl);

    SplitArgs sa;
    sa.src[0] = s;   sa.hi[0] = sh;  sa.lo[0] = sl;
    sa.src[1] = kin; sa.hi[1] = xh;  sa.lo[1] = xl;
    sa.src[2] = Wq;  sa.hi[2] = wqh; sa.lo[2] = wql;
    sa.src[3] = Wk;  sa.hi[3] = wkh; sa.lo[3] = wkl;
    sa.src[4] = Wv;  sa.hi[4] = wvh; sa.lo[4] = wvl;
    sa.src[5] = Wg;  sa.hi[5] = wgh; sa.lo[5] = wgl;
    sa.src[6] = Wo;  sa.hi[6] = woh; sa.lo[6] = wol;
    split7<<<dim3(256, 7), 256>>>(sa);

    cudaFuncSetAttribute(gemm_tc4, cudaFuncAttributeMaxDynamicSharedMemorySize, GEMM_SMEM);
    gemm_tc4<<<dim3(8, 8, 4), 256, GEMM_SMEM>>>(
        sh, sl, xh, xl, wqh, wql, wkh, wkl, wvh, wvl, wgh, wgl, bq,
        qbh, qbl, kbh, kbl, vbh, vbl, g);

    cudaFuncSetAttribute(zbias_kernel, cudaFuncAttributeMaxDynamicSharedMemorySize, ZB_SMEM);
    zbias_kernel<<<dim3(NI / 2, NJ / 256), 256, ZB_SMEM>>>(bias, Wz, mask, z);

    cudaFuncSetAttribute(attn_mma, cudaFuncAttributeMaxDynamicSharedMemorySize, AT_SMEM);
    attn_mma<<<dim3(NH, NI / 64), 128, AT_SMEM>>>(
        qbh, qbl, kbh, kbl, vbh, vbl, z, g, goh, gol);

    cudaFuncSetAttribute(gemm_out64, cudaFuncAttributeMaxDynamicSharedMemorySize, G64_SMEM);
    gemm_out64<<<dim3(CS / 128, NI / 64), 256, G64_SMEM>>>(goh, gol, woh, wol, out);
}

// round 13
// speedup vs baseline: 1.4205x; 1.0123x over previous
#include <cuda_runtime.h>
#include <cuda_bf16.h>
#include <math.h>
#include <stdint.h>

#define CS 1024
#define CZ 128
#define NH 16
#define HD 64
#define NI 1024
#define NJ 1024
#define NELEM (NI * CS)

// ---------------- scratch (device globals; no allocation allowed) ----------------
__device__ float g_g[NELEM];
__device__ __nv_bfloat16 g_z[(size_t)NH * NI * NJ];   // 32 MB (bf16 now)

// bf16 hi/lo split buffers (inputs + weights)
__device__ __nv_bfloat16 g_sh[NELEM],  g_sl[NELEM];     // s
__device__ __nv_bfloat16 g_xh[NELEM],  g_xl[NELEM];     // k_in
__device__ __nv_bfloat16 g_wqh[NELEM], g_wql[NELEM];
__device__ __nv_bfloat16 g_wkh[NELEM], g_wkl[NELEM];
__device__ __nv_bfloat16 g_wvh[NELEM], g_wvl[NELEM];
__device__ __nv_bfloat16 g_wgh[NELEM], g_wgl[NELEM];
__device__ __nv_bfloat16 g_woh[NELEM], g_wol[NELEM];
__device__ __nv_bfloat16 g_goh[NELEM], g_gol[NELEM];    // g (*) o  (written by attn epilogue)
// q/k/v hi/lo (written directly by projection epilogue)
__device__ __nv_bfloat16 g_qbh[NELEM], g_qbl[NELEM];
__device__ __nv_bfloat16 g_kbh[NELEM], g_kbl[NELEM];
__device__ __nv_bfloat16 g_vbh[NELEM], g_vbl[NELEM];

// =====================================================================
// helpers (baseline PTX only — NO tcgen05 on this toolchain path)
// =====================================================================
__device__ __forceinline__ uint32_t smem_u32(const void* p) {
    uint32_t a;
    asm("{ .reg .u64 t; cvta.to.shared.u64 t, %1; cvt.u32.u64 %0, t; }"
        : "=r"(a) : "l"(p));
    return a;
}

__device__ __forceinline__ void cp16(uint32_t dst, const void* src) {
    uint64_t g;
    asm("cvta.to.global.u64 %0, %1;" : "=l"(g) : "l"(src));
    asm volatile("cp.async.cg.shared.global [%0], [%1], 16;" :: "r"(dst), "l"(g));
}

__device__ __forceinline__ void ldm_x4(uint32_t* r, uint32_t addr) {
    asm volatile("ldmatrix.sync.aligned.m8n8.x4.shared.b16 {%0,%1,%2,%3}, [%4];"
        : "=r"(r[0]), "=r"(r[1]), "=r"(r[2]), "=r"(r[3]) : "r"(addr));
}

__device__ __forceinline__ void ldm_x4t(uint32_t* r, uint32_t addr) {
    asm volatile("ldmatrix.sync.aligned.m8n8.x4.trans.shared.b16 {%0,%1,%2,%3}, [%4];"
        : "=r"(r[0]), "=r"(r[1]), "=r"(r[2]), "=r"(r[3]) : "r"(addr));
}

__device__ __forceinline__ void mma16816(float* d, const uint32_t* a, const uint32_t* b) {
    asm volatile(
        "mma.sync.aligned.m16n8k16.row.col.f32.bf16.bf16.f32 "
        "{%0,%1,%2,%3}, {%4,%5,%6,%7}, {%8,%9}, {%0,%1,%2,%3};"
        : "+f"(d[0]), "+f"(d[1]), "+f"(d[2]), "+f"(d[3])
        : "r"(a[0]), "r"(a[1]), "r"(a[2]), "r"(a[3]), "r"(b[0]), "r"(b[1]));
}

__device__ __forceinline__ uint32_t swz(uint32_t off) {
    return off ^ ((off >> 3) & 0x70);
}

// FMA-pipe exp (no MUFU): exp(x) = 2^(x*log2e), poly on [-0.5,0.5]
__device__ __forceinline__ float fexp(float x) {
    float t = fmaxf(x * 1.4426950408889634f, -126.0f);
    float zz = t + 12582912.0f;              // 1.5 * 2^23 magic round
    int   ii = __float_as_int(zz) - 0x4B400000;
    float f  = t - (zz - 12582912.0f);
    float p  = 1.3333558146e-3f;
    p = fmaf(p, f, 9.6181291076e-3f);
    p = fmaf(p, f, 5.5504108664e-2f);
    p = fmaf(p, f, 2.4022650696e-1f);
    p = fmaf(p, f, 6.9314718056e-1f);
    p = fmaf(p, f, 1.0f);
    return __int_as_float(__float_as_int(p) + (ii << 23));
}

__device__ __forceinline__ uint32_t pk_hi(float a, float b) {
    __nv_bfloat162 t;
    t.x = __float2bfloat16(a); t.y = __float2bfloat16(b);
    return *(uint32_t*)&t;
}
__device__ __forceinline__ uint32_t pk_lo(float a, float b) {
    __nv_bfloat16 ha = __float2bfloat16(a), hb = __float2bfloat16(b);
    __nv_bfloat162 t;
    t.x = __float2bfloat16(a - __bfloat162float(ha));
    t.y = __float2bfloat16(b - __bfloat162float(hb));
    return *(uint32_t*)&t;
}

// =====================================================================
// split conversion: x -> (hi=bf16(x), lo=bf16(x-hi))
// =====================================================================
struct SplitArgs {
    const float* src[7];
    __nv_bfloat16* hi[7];
    __nv_bfloat16* lo[7];
};

__device__ __forceinline__ void split4(float4 v, __nv_bfloat162* hi2,
                                       __nv_bfloat162* lo2, size_t i) {
    __nv_bfloat16 h0 = __float2bfloat16(v.x);
    __nv_bfloat16 h1 = __float2bfloat16(v.y);
    __nv_bfloat16 h2 = __float2bfloat16(v.z);
    __nv_bfloat16 h3 = __float2bfloat16(v.w);
    __nv_bfloat16 l0 = __float2bfloat16(v.x - __bfloat162float(h0));
    __nv_bfloat16 l1 = __float2bfloat16(v.y - __bfloat162float(h1));
    __nv_bfloat16 l2 = __float2bfloat16(v.z - __bfloat162float(h2));
    __nv_bfloat16 l3 = __float2bfloat16(v.w - __bfloat162float(h3));
    __nv_bfloat162 ph0; ph0.x = h0; ph0.y = h1;
    __nv_bfloat162 ph1; ph1.x = h2; ph1.y = h3;
    __nv_bfloat162 pl0; pl0.x = l0; pl0.y = l1;
    __nv_bfloat162 pl1; pl1.x = l2; pl1.y = l3;
    hi2[2 * i] = ph0; hi2[2 * i + 1] = ph1;
    lo2[2 * i] = pl0; lo2[2 * i + 1] = pl1;
}

__global__ __launch_bounds__(256) void split7(SplitArgs a) {
    const float4* src = (const float4*)a.src[blockIdx.y];
    __nv_bfloat162* hi2 = (__nv_bfloat162*)a.hi[blockIdx.y];
    __nv_bfloat162* lo2 = (__nv_bfloat162*)a.lo[blockIdx.y];
    int t = blockIdx.x * 256 + threadIdx.x;
    for (size_t i = t; i < NELEM / 4; i += 256 * 256)
        split4(src[i], hi2, lo2, i);
}

// =====================================================================
// bf16-split GEMM (projections): 128(M) x 64(N) tiles, BK=64,
// 2-stage cp.async, 48KB/stage -> 97KB/CTA -> 2 CTAs/SM.
// 8 warps as 4(M:32) x 2(N:32).
// =====================================================================
#define G4_SSZ 49152
#define G4_SMEM (2 * G4_SSZ + 1024)

__device__ __forceinline__ void load_stage_g4(
    uint32_t sbase, int s, int tid,
    const __nv_bfloat16* Ah, const __nv_bfloat16* Al,
    const __nv_bfloat16* Bh, const __nv_bfloat16* Bl,
    int m0, int n0)
{
    uint32_t sb = sbase + (uint32_t)(s & 1) * G4_SSZ;
    int k0 = s * 64;
#pragma unroll
    for (int p = 0; p < 8; p++) {          // A hi/lo: 128 rows x 8 chunks x 2
        int slot = tid + 256 * p;
        int arr = slot >> 10, idx = slot & 1023;
        int row = idx >> 3, ch = idx & 7;
        cp16(sb + (uint32_t)arr * 16384u + swz((uint32_t)(row * 128 + ch * 16)),
             (arr ? Al : Ah) + (size_t)(m0 + row) * CS + k0 + ch * 8);
    }
#pragma unroll
    for (int p = 0; p < 4; p++) {          // B hi/lo: 64 rows x 8 chunks x 2
        int slot = tid + 256 * p;
        int arr = slot >> 9, idx = slot & 511;
        int row = idx >> 3, ch = idx & 7;
        cp16(sb + 32768u + (uint32_t)arr * 8192u + swz((uint32_t)(row * 128 + ch * 16)),
             (arr ? Bl : Bh) + (size_t)(n0 + row) * CS + k0 + ch * 8);
    }
}

template <int MODE, int OUT>   // MODE: 0 plain,1 +bias,2 sigmoid; OUT: 0 fp32, 1 bf16 hi/lo
__device__ void gemm_mma64_core(
    const __nv_bfloat16* Ah, const __nv_bfloat16* Al,
    const __nv_bfloat16* Bh, const __nv_bfloat16* Bl,
    const float* bvec, float* C,
    __nv_bfloat16* Ch, __nv_bfloat16* Cl, int m0, int n0)
{
    extern __shared__ __align__(16) char dsm[];
    const int tid = threadIdx.x;
    uint32_t sbase = smem_u32(dsm);
    sbase = (sbase + 1023u) & ~1023u;

    const int w  = tid >> 5;
    const int ln = tid & 31;
    const int wm = w & 3;        // 4 warps over M: 32 rows each
    const int wn = w >> 2;       // 2 warps over N: 32 cols each

    float acc[2][4][4];
#pragma unroll
    for (int mt = 0; mt < 2; mt++)
#pragma unroll
        for (int nt = 0; nt < 4; nt++)
#pragma unroll
            for (int e = 0; e < 4; e++) acc[mt][nt][e] = 0.f;

    load_stage_g4(sbase, 0, tid, Ah, Al, Bh, Bl, m0, n0);
    asm volatile("cp.async.commit_group;" ::: "memory");

    const int a_row = wm * 32 + (ln & 15);
    const int a_kb  = (ln >> 4) * 16;
    const int b_row = wn * 32 + (ln & 7) + ((ln >> 4) & 1) * 8;
    const int b_kb  = ((ln >> 3) & 1) * 16;

    for (int s = 0; s < 16; s++) {
        if (s + 1 < 16) {
            load_stage_g4(sbase, s + 1, tid, Ah, Al, Bh, Bl, m0, n0);
            asm volatile("cp.async.commit_group;" ::: "memory");
            asm volatile("cp.async.wait_group 1;" ::: "memory");
        } else {
            asm volatile("cp.async.wait_group 0;" ::: "memory");
        }
        __syncthreads();

        uint32_t sb = sbase + (uint32_t)(s & 1) * G4_SSZ;
#pragma unroll
        for (int kk = 0; kk < 4; kk++) {
            uint32_t ah[2][4], al[2][4], bh[4][2], bl[4][2];
#pragma unroll
            for (int mt = 0; mt < 2; mt++) {
                uint32_t off = swz((uint32_t)((a_row + mt * 16) * 128 + kk * 32 + a_kb));
                ldm_x4(ah[mt], sb + off);
                ldm_x4(al[mt], sb + 16384u + off);
            }
#pragma unroll
            for (int np = 0; np < 2; np++) {
                uint32_t off = swz((uint32_t)((b_row + np * 16) * 128 + kk * 32 + b_kb));
                uint32_t t4[4];
                ldm_x4(t4, sb + 32768u + off);
                bh[2 * np][0] = t4[0]; bh[2 * np][1] = t4[1];
                bh[2 * np + 1][0] = t4[2]; bh[2 * np + 1][1] = t4[3];
                ldm_x4(t4, sb + 40960u + off);
                bl[2 * np][0] = t4[0]; bl[2 * np][1] = t4[1];
                bl[2 * np + 1][0] = t4[2]; bl[2 * np + 1][1] = t4[3];
            }
#pragma unroll
            for (int mt = 0; mt < 2; mt++)
#pragma unroll
                for (int nt = 0; nt < 4; nt++) {
                    mma16816(acc[mt][nt], ah[mt], bh[nt]);
                    mma16816(acc[mt][nt], al[mt], bh[nt]);
                    mma16816(acc[mt][nt], ah[mt], bl[nt]);
                }
        }
        __syncthreads();   // all warps done with buf (s&1) before it's reloaded at s+2
    }

    const int er = ln >> 2;
    const int ec = (ln & 3) * 2;
#pragma unroll
    for (int mt = 0; mt < 2; mt++) {
#pragma unroll
        for (int nt = 0; nt < 4; nt++) {
            int m = m0 + wm * 32 + mt * 16 + er;
            int n = n0 + wn * 32 + nt * 8 + ec;
#pragma unroll
            for (int half = 0; half < 2; half++) {
                float2 r;
                r.x = acc[mt][nt][2 * half + 0];
                r.y = acc[mt][nt][2 * half + 1];
                if (MODE == 1) { r.x += bvec[n]; r.y += bvec[n + 1]; }
                else if (MODE == 2) {
                    r.x = 1.f / (1.f + __expf(-r.x));
                    r.y = 1.f / (1.f + __expf(-r.y));
                }
                size_t idx = (size_t)(m + half * 8) * CS + n;
                if (OUT == 0) {
                    *(float2*)(C + idx) = r;
                } else {
                    uint32_t uh = pk_hi(r.x, r.y), ul = pk_lo(r.x, r.y);
                    *(uint32_t*)(Ch + idx) = uh;
                    *(uint32_t*)(Cl + idx) = ul;
                }
            }
        }
    }
}

__global__ __launch_bounds__(256, 2) void gemm_tc4(
    const __nv_bfloat16* sh,  const __nv_bfloat16* sl,
    const __nv_bfloat16* xh,  const __nv_bfloat16* xl,
    const __nv_bfloat16* wqh, const __nv_bfloat16* wql,
    const __nv_bfloat16* wkh, const __nv_bfloat16* wkl,
    const __nv_bfloat16* wvh, const __nv_bfloat16* wvl,
    const __nv_bfloat16* wgh, const __nv_bfloat16* wgl,
    const float* bq,
    __nv_bfloat16* qbh, __nv_bfloat16* qbl,
    __nv_bfloat16* kbh, __nv_bfloat16* kbl,
    __nv_bfloat16* vbh, __nv_bfloat16* vbl,
    float* g)
{
    int m0 = blockIdx.y * 128, n0 = blockIdx.x * 64;
    switch (blockIdx.z) {
        case 0:  gemm_mma64_core<1, 1>(sh, sl, wqh, wql, bq, nullptr, qbh, qbl, m0, n0); break;
        case 1:  gemm_mma64_core<0, 1>(xh, xl, wkh, wkl, nullptr, nullptr, kbh, kbl, m0, n0); break;
        case 2:  gemm_mma64_core<0, 1>(xh, xl, wvh, wvl, nullptr, nullptr, vbh, vbl, m0, n0); break;
        default: gemm_mma64_core<2, 0>(sh, sl, wgh, wgl, nullptr, g, nullptr, nullptr, m0, n0); break;
    }
}

// =====================================================================
// Output GEMM: BM=64 x BN=128 tiles -> 128 CTAs (one full wave), 3-stage
// =====================================================================
#define G64_SSZ 49152
#define G64_SMEM (3 * G64_SSZ + 1024)

__device__ __forceinline__ void load_stage64(
    uint32_t sbase, int s, int tid,
    const __nv_bfloat16* Ah, const __nv_bfloat16* Al,
    const __nv_bfloat16* Bh, const __nv_bfloat16* Bl,
    int m0, int n0)
{
    uint32_t sb = sbase + (uint32_t)(s % 3) * G64_SSZ;
    int k0 = s * 64;
#pragma unroll
    for (int p = 0; p < 4; p++) {          // A hi/lo: 64 rows x 8 x 2
        int slot = tid + 256 * p;
        int arr = slot >> 9, idx = slot & 511;
        int row = idx >> 3, ch = idx & 7;
        cp16(sb + (uint32_t)arr * 8192u + swz((uint32_t)(row * 128 + ch * 16)),
             (arr ? Al : Ah) + (size_t)(m0 + row) * CS + k0 + ch * 8);
    }
#pragma unroll
    for (int p = 0; p < 8; p++) {          // B hi/lo: 128 rows x 8 x 2
        int slot = tid + 256 * p;
        int arr = slot >> 10, idx = slot & 1023;
        int row = idx >> 3, ch = idx & 7;
        cp16(sb + 16384u + (uint32_t)arr * 16384u + swz((uint32_t)(row * 128 + ch * 16)),
             (arr ? Bl : Bh) + (size_t)(n0 + row) * CS + k0 + ch * 8);
    }
}

__global__ __launch_bounds__(256, 1) void gemm_out64(
    const __nv_bfloat16* Ah, const __nv_bfloat16* Al,
    const __nv_bfloat16* Bh, const __nv_bfloat16* Bl,
    float* out)
{
    extern __shared__ __align__(16) char dsm[];
    const int tid = threadIdx.x;
    uint32_t sbase = smem_u32(dsm);
    sbase = (sbase + 1023u) & ~1023u;
    const int m0 = blockIdx.y * 64, n0 = blockIdx.x * 128;

    const int w = tid >> 5, ln = tid & 31;
    const int wm = w & 1;        // 2 warps over M (32 rows)
    const int wn = w >> 1;       // 4 warps over N (32 cols)

    float acc[2][4][4];
#pragma unroll
    for (int mt = 0; mt < 2; mt++)
#pragma unroll
        for (int nt = 0; nt < 4; nt++)
#pragma unroll
            for (int e = 0; e < 4; e++) acc[mt][nt][e] = 0.f;

    load_stage64(sbase, 0, tid, Ah, Al, Bh, Bl, m0, n0);
    asm volatile("cp.async.commit_group;" ::: "memory");
    load_stage64(sbase, 1, tid, Ah, Al, Bh, Bl, m0, n0);
    asm volatile("cp.async.commit_group;" ::: "memory");

    const int a_row = wm * 32 + (ln & 15);
    const int a_kb  = (ln >> 4) * 16;
    const int b_row = wn * 32 + (ln & 7) + ((ln >> 4) & 1) * 8;
    const int b_kb  = ((ln >> 3) & 1) * 16;

    for (int s = 0; s < 16; s++) {
        if (s < 15) asm volatile("cp.async.wait_group 1;" ::: "memory");
        else        asm volatile("cp.async.wait_group 0;" ::: "memory");
        __syncthreads();

        uint32_t sb = sbase + (uint32_t)(s % 3) * G64_SSZ;
#pragma unroll
        for (int kk = 0; kk < 4; kk++) {
            uint32_t ah4[2][4], al4[2][4], bh[4][2], bl[4][2];
#pragma unroll
            for (int mt = 0; mt < 2; mt++) {
                uint32_t off = swz((uint32_t)((a_row + mt * 16) * 128 + kk * 32 + a_kb));
                ldm_x4(ah4[mt], sb + off);
                ldm_x4(al4[mt], sb + 8192u + off);
            }
#pragma unroll
            for (int np = 0; np < 2; np++) {
                uint32_t off = swz((uint32_t)((b_row + np * 16) * 128 + kk * 32 + b_kb));
                uint32_t t4[4];
                ldm_x4(t4, sb + 16384u + off);
                bh[2 * np][0] = t4[0]; bh[2 * np][1] = t4[1];
                bh[2 * np + 1][0] = t4[2]; bh[2 * np + 1][1] = t4[3];
                ldm_x4(t4, sb + 32768u + off);
                bl[2 * np][0] = t4[0]; bl[2 * np][1] = t4[1];
                bl[2 * np + 1][0] = t4[2]; bl[2 * np + 1][1] = t4[3];
            }
#pragma unroll
            for (int mt = 0; mt < 2; mt++)
#pragma unroll
                for (int nt = 0; nt < 4; nt++) {
                    mma16816(acc[mt][nt], ah4[mt], bh[nt]);
                    mma16816(acc[mt][nt], al4[mt], bh[nt]);
                    mma16816(acc[mt][nt], ah4[mt], bl[nt]);
                }
        }

        if (s + 2 < 16) {
            load_stage64(sbase, s + 2, tid, Ah, Al, Bh, Bl, m0, n0);
            asm volatile("cp.async.commit_group;" ::: "memory");
        }
    }

    const int er = ln >> 2, ec = (ln & 3) * 2;
#pragma unroll
    for (int mt = 0; mt < 2; mt++)
#pragma unroll
        for (int nt = 0; nt < 4; nt++) {
            int m = m0 + wm * 32 + mt * 16 + er;
            int n = n0 + wn * 32 + nt * 8 + ec;
            float2 r0; r0.x = acc[mt][nt][0]; r0.y = acc[mt][nt][1];
            float2 r1; r1.x = acc[mt][nt][2]; r1.y = acc[mt][nt][3];
            *(float2*)(out + (size_t)m * CS + n) = r0;
            *(float2*)(out + (size_t)(m + 8) * CS + n) = r1;
        }
}

// ---------------- z kernel (writes bf16 z) ----------------
#define ZB_SMEM ((2 * 256 * 33 + CZ * NH) * 4)
__global__ __launch_bounds__(256) void zbias_kernel(
    const float* __restrict__ bias, const float* __restrict__ Wz,
    const float* __restrict__ mask, __nv_bfloat16* __restrict__ z)
{
    extern __shared__ float sm[];
    float* bs = sm;
    float* wzs = sm + 2 * 256 * 33;

    const int tid = threadIdx.x;
    const int jg = tid & 31;
    const int hg = (tid >> 5) & 3;
    const int ig = tid >> 7;
    const int i0 = blockIdx.x * 2;
    const int j0 = blockIdx.y * 256;

    for (int t = tid; t < CZ * NH; t += 256) wzs[t] = Wz[t];

    float acc[8][4];
#pragma unroll
    for (int kk = 0; kk < 8; kk++)
#pragma unroll
        for (int hh = 0; hh < 4; hh++) acc[kk][hh] = 0.f;

    for (int cc = 0; cc < CZ; cc += 32) {
        __syncthreads();
#pragma unroll
        for (int p = 0; p < 16; p++) {
            int slot = tid + 256 * p;
            int c4 = slot & 7;
            int row = slot >> 3;
            int ii = row >> 8;
            int j = row & 255;
            float4 vv = *(const float4*)(bias +
                ((size_t)(i0 + ii) * NJ + (j0 + j)) * CZ + cc + c4 * 4);
            float* dst = bs + ((size_t)ii * 256 + j) * 33 + c4 * 4;
            dst[0] = vv.x; dst[1] = vv.y; dst[2] = vv.z; dst[3] = vv.w;
        }
        __syncthreads();

#pragma unroll
        for (int c = 0; c < 32; c++) {
            const float* wrow = wzs + (cc + c) * NH + hg * 4;
            float w0 = wrow[0], w1 = wrow[1], w2 = wrow[2], w3 = wrow[3];
#pragma unroll
            for (int kk = 0; kk < 8; kk++) {
                float bv = bs[((size_t)ig * 256 + (jg + 32 * kk)) * 33 + c];
                acc[kk][0] += bv * w0;
                acc[kk][1] += bv * w1;
                acc[kk][2] += bv * w2;
                acc[kk][3] += bv * w3;
            }
        }
    }

    const int i = i0 + ig;
#pragma unroll
    for (int hh = 0; hh < 4; hh++) {
        int h = hg * 4 + hh;
        size_t base = ((size_t)h * NI + i) * NJ;
#pragma unroll
        for (int kk = 0; kk < 8; kk++) {
            int j = j0 + jg + 32 * kk;
            z[base + j] = __float2bfloat16(
                acc[kk][hh] + (1.f - mask[j]) * (-1000000.0f));
        }
    }
}

// =====================================================================
// Flash attention v3: CTA = (head, 64 i-rows), 128 threads (4 warps),
// 2 CTAs/SM. z (bf16) read directly from GMEM.
// =====================================================================
#define AQ_H 0
#define AQ_L 8192
#define ASTG 16384
#define SKH 0
#define SKL 8192
#define SVH 16384
#define SVL 24576
#define SSZ 32768
#define AT_SMEM (ASTG + 2 * SSZ)     /* 81920 */

__device__ __forceinline__ void attn_load_kv(
    uint32_t sb, int stage, int j0, int h, int tid,
    const __nv_bfloat16* kh, const __nv_bfloat16* kl,
    const __nv_bfloat16* vh, const __nv_bfloat16* vl)
{
    uint32_t stg = sb + ASTG + (uint32_t)stage * SSZ;
#pragma unroll
    for (int p = 0; p < 16; p++) {
        int slot = tid + 128 * p;
        int arr = slot >> 9, idx = slot & 511;
        int row = idx >> 3, ch = idx & 7;
        const __nv_bfloat16* base =
            (arr == 0) ? kh : (arr == 1) ? kl : (arr == 2) ? vh : vl;
        cp16(stg + (uint32_t)arr * 8192u + swz((uint32_t)(row * 128 + ch * 16)),
             base + (size_t)(j0 + row) * CS + h * HD + ch * 8);
    }
}

__global__ __launch_bounds__(128, 2) void attn_mma(
    const __nv_bfloat16* __restrict__ qh_g, const __nv_bfloat16* __restrict__ ql_g,
    const __nv_bfloat16* __restrict__ kh_g, const __nv_bfloat16* __restrict__ kl_g,
    const __nv_bfloat16* __restrict__ vh_g, const __nv_bfloat16* __restrict__ vl_g,
    const __nv_bfloat16* __restrict__ z, const float* __restrict__ g,
    __nv_bfloat16* __restrict__ goh, __nv_bfloat16* __restrict__ gol)
{
    extern __shared__ __align__(16) char smra[];
    uint32_t sb = smem_u32(smra);
    const int h = blockIdx.x;
    const int i0 = blockIdx.y * 64;
    const int tid = threadIdx.x;
    const int w = tid >> 5, ln = tid & 31;
    const int r0 = w * 16;               // warp's 16 rows (4 warps x 16 = 64)
    const int er = ln >> 2, ec = (ln & 3) * 2;

    // Q hi/lo (64 x 64 bf16 each): 1024 chunks / 128 threads = 8 per thread
#pragma unroll
    for (int p = 0; p < 8; p++) {
        int slot = tid + 128 * p;
        int arr = slot >> 9, idx = slot & 511;
        int row = idx >> 3, ch = idx & 7;
        cp16(sb + (arr ? AQ_L : AQ_H) + swz((uint32_t)(row * 128 + ch * 16)),
             (arr ? ql_g : qh_g) + (size_t)(i0 + row) * CS + h * HD + ch * 8);
    }
    attn_load_kv(sb, 0, 0, h, tid, kh_g, kl_g, vh_g, vl_g);
    asm volatile("cp.async.commit_group;" ::: "memory");

    // row pointers for direct bf16 z loads (rows rA, rB of this thread)
    const __nv_bfloat16* zA = z + ((size_t)h * NI + i0 + r0 + er) * NJ + ec;
    const __nv_bfloat16* zB = zA + (size_t)8 * NJ;

    float mrow0 = -3.0e38f, mrow1 = -3.0e38f, lrow0 = 0.f, lrow1 = 0.f;
    float accO[8][4];
#pragma unroll
    for (int nt = 0; nt < 8; nt++)
#pragma unroll
        for (int e = 0; e < 4; e++) accO[nt][e] = 0.f;

    for (int jt = 0; jt < 16; jt++) {
        const int j0 = jt * 64;
        if (jt > 0) __syncthreads();     // all warps done with buffer (jt+1)&1
        if (jt + 1 < 16) {
            attn_load_kv(sb, (jt + 1) & 1, (jt + 1) * 64, h, tid,
                         kh_g, kl_g, vh_g, vl_g);
            asm volatile("cp.async.commit_group;" ::: "memory");
            asm volatile("cp.async.wait_group 1;" ::: "memory");
        } else {
            asm volatile("cp.async.wait_group 0;" ::: "memory");
        }
        __syncthreads();

        // issue z loads early (independent; latency hidden under QK MMAs)
        float2 zr0[8], zr1[8];
#pragma unroll
        for (int nt = 0; nt < 8; nt++) {
            __nv_bfloat162 b0 = *(const __nv_bfloat162*)&zA[j0 + nt * 8];
            __nv_bfloat162 b1 = *(const __nv_bfloat162*)&zB[j0 + nt * 8];
            zr0[nt] = __bfloat1622float2(b0);
            zr1[nt] = __bfloat1622float2(b1);
        }

        uint32_t stg = sb + ASTG + (uint32_t)(jt & 1) * SSZ;

        // ---- QK: S = Q @ K^T (3-term) ----
        float accS[8][4];
#pragma unroll
        for (int nt = 0; nt < 8; nt++)
#pragma unroll
            for (int e = 0; e < 4; e++) accS[nt][e] = 0.f;

#pragma unroll
        for (int kk = 0; kk < 4; kk++) {
            uint32_t qh4[4], ql4[4];
            uint32_t offq = swz((uint32_t)((r0 + (ln & 15)) * 128
                                           + kk * 32 + (ln >> 4) * 16));
            ldm_x4(qh4, sb + AQ_H + offq);
            ldm_x4(ql4, sb + AQ_L + offq);
#pragma unroll
            for (int np = 0; np < 4; np++) {
                uint32_t offk = swz((uint32_t)((np * 16 + (ln & 7) + ((ln >> 4) & 1) * 8) * 128
                                               + kk * 32 + ((ln >> 3) & 1) * 16));
                uint32_t th[4], tl[4];
                ldm_x4(th, stg + SKH + offk);
                ldm_x4(tl, stg + SKL + offk);
                mma16816(accS[2 * np], qh4, th);
                mma16816(accS[2 * np], ql4, th);
                mma16816(accS[2 * np], qh4, tl);
                mma16816(accS[2 * np + 1], qh4, th + 2);
                mma16816(accS[2 * np + 1], ql4, th + 2);
                mma16816(accS[2 * np + 1], qh4, tl + 2);
            }
        }

        // ---- scale + z, row max (register softmax) ----
        float mx0 = -3.0e38f, mx1 = -3.0e38f;
#pragma unroll
        for (int nt = 0; nt < 8; nt++) {
            accS[nt][0] = fmaf(accS[nt][0], 0.125f, zr0[nt].x);
            accS[nt][1] = fmaf(accS[nt][1], 0.125f, zr0[nt].y);
            accS[nt][2] = fmaf(accS[nt][2], 0.125f, zr1[nt].x);
            accS[nt][3] = fmaf(accS[nt][3], 0.125f, zr1[nt].y);
            mx0 = fmaxf(mx0, fmaxf(accS[nt][0], accS[nt][1]));
            mx1 = fmaxf(mx1, fmaxf(accS[nt][2], accS[nt][3]));
        }
        mx0 = fmaxf(mx0, __shfl_xor_sync(0xffffffffu, mx0, 1));
        mx0 = fmaxf(mx0, __shfl_xor_sync(0xffffffffu, mx0, 2));
        mx1 = fmaxf(mx1, __shfl_xor_sync(0xffffffffu, mx1, 1));
        mx1 = fmaxf(mx1, __shfl_xor_sync(0xffffffffu, mx1, 2));
        float mn0 = fmaxf(mrow0, mx0), mn1 = fmaxf(mrow1, mx1);
        float sc0 = fexp(mrow0 - mn0), sc1 = fexp(mrow1 - mn1);
        mrow0 = mn0; mrow1 = mn1;

        float sum0 = 0.f, sum1 = 0.f;
#pragma unroll
        for (int nt = 0; nt < 8; nt++) {
            accS[nt][0] = fexp(accS[nt][0] - mn0);
            accS[nt][1] = fexp(accS[nt][1] - mn0);
            accS[nt][2] = fexp(accS[nt][2] - mn1);
            accS[nt][3] = fexp(accS[nt][3] - mn1);
            sum0 += accS[nt][0] + accS[nt][1];
            sum1 += accS[nt][2] + accS[nt][3];
            accO[nt][0] *= sc0; accO[nt][1] *= sc0;
            accO[nt][2] *= sc1; accO[nt][3] *= sc1;
        }
        sum0 += __shfl_xor_sync(0xffffffffu, sum0, 1);
        sum0 += __shfl_xor_sync(0xffffffffu, sum0, 2);
        sum1 += __shfl_xor_sync(0xffffffffu, sum1, 1);
        sum1 += __shfl_xor_sync(0xffffffffu, sum1, 2);
        lrow0 = lrow0 * sc0 + sum0;
        lrow1 = lrow1 * sc1 + sum1;

        // ---- in-register P -> A-frag repack (hi/lo) ----
        uint32_t pah[4][4], pal[4][4];
#pragma unroll
        for (int kk = 0; kk < 4; kk++) {
            pah[kk][0] = pk_hi(accS[2 * kk][0], accS[2 * kk][1]);
            pah[kk][1] = pk_hi(accS[2 * kk][2], accS[2 * kk][3]);
            pah[kk][2] = pk_hi(accS[2 * kk + 1][0], accS[2 * kk + 1][1]);
            pah[kk][3] = pk_hi(accS[2 * kk + 1][2], accS[2 * kk + 1][3]);
            pal[kk][0] = pk_lo(accS[2 * kk][0], accS[2 * kk][1]);
            pal[kk][1] = pk_lo(accS[2 * kk][2], accS[2 * kk][3]);
            pal[kk][2] = pk_lo(accS[2 * kk + 1][0], accS[2 * kk + 1][1]);
            pal[kk][3] = pk_lo(accS[2 * kk + 1][2], accS[2 * kk + 1][3]);
        }

        // ---- PV: O += P @ V (3-term, V via ldmatrix.trans) ----
#pragma unroll
        for (int kk = 0; kk < 4; kk++) {
#pragma unroll
            for (int np = 0; np < 4; np++) {
                uint32_t ov = swz((uint32_t)((kk * 16 + (ln & 7) + ((ln >> 3) & 1) * 8) * 128
                                             + (np * 16 + ((ln >> 4) & 1) * 8) * 2));
                uint32_t th[4], tl[4];
                ldm_x4t(th, stg + SVH + ov);
                ldm_x4t(tl, stg + SVL + ov);
                mma16816(accO[2 * np], pah[kk], th);
                mma16816(accO[2 * np], pal[kk], th);
                mma16816(accO[2 * np], pah[kk], tl);
                mma16816(accO[2 * np + 1], pah[kk], th + 2);
                mma16816(accO[2 * np + 1], pal[kk], th + 2);
                mma16816(accO[2 * np + 1], pah[kk], tl + 2);
            }
        }
    }

    // ---- epilogue: o = accO/l, fused with g (*) . , split to bf16 hi/lo ----
    float inv0 = 1.f / lrow0, inv1 = 1.f / lrow1;
    const int rowA = i0 + r0 + er;
#pragma unroll
    for (int nt = 0; nt < 8; nt++) {
        int col = h * HD + nt * 8 + ec;
        float2 gv0 = *(const float2*)&g[(size_t)rowA * CS + col];
        float2 gv1 = *(const float2*)&g[(size_t)(rowA + 8) * CS + col];
        float x0 = accO[nt][0] * inv0 * gv0.x;
        float x1 = accO[nt][1] * inv0 * gv0.y;
        float x2 = accO[nt][2] * inv1 * gv1.x;
        float x3 = accO[nt][3] * inv1 * gv1.y;
        uint32_t h0 = pk_hi(x0, x1), l0 = pk_lo(x0, x1);
        uint32_t h1 = pk_hi(x2, x3), l1 = pk_lo(x2, x3);
        *(uint32_t*)(goh + (size_t)rowA * CS + col) = h0;
        *(uint32_t*)(gol + (size_t)rowA * CS + col) = l0;
        *(uint32_t*)(goh + (size_t)(rowA + 8) * CS + col) = h1;
        *(uint32_t*)(gol + (size_t)(rowA + 8) * CS + col) = l1;
    }
}

// ---------------- launch (serial, single stream) ----------------
extern "C" void kernel_launch(void* const* d_in, const int* in_sizes, int n_in,
                              void* d_out, int out_size)
{
    const float* s    = (const float*)d_in[0];
    const float* kin  = (const float*)d_in[1];
    const float* mask = (const float*)d_in[2];
    const float* bias = (const float*)d_in[3];
    const float* Wq   = (const float*)d_in[4];
    const float* bq   = (const float*)d_in[5];
    const float* Wk   = (const float*)d_in[6];
    const float* Wv   = (const float*)d_in[7];
    const float* Wg   = (const float*)d_in[8];
    const float* Wo   = (const float*)d_in[9];
    const float* Wz   = (const float*)d_in[10];
    float* out = (float*)d_out;

    float* g;
    __nv_bfloat16* z;
    cudaGetSymbolAddress((void**)&g, g_g);
    cudaGetSymbolAddress((void**)&z, g_z);

    __nv_bfloat16 *sh, *sl, *xh, *xl, *wqh, *wql, *wkh, *wkl,
                  *wvh, *wvl, *wgh, *wgl, *woh, *wol, *goh, *gol,
                  *qbh, *qbl, *kbh, *kbl, *vbh, *vbl;
    cudaGetSymbolAddress((void**)&sh,  g_sh);  cudaGetSymbolAddress((void**)&sl,  g_sl);
    cudaGetSymbolAddress((void**)&xh,  g_xh);  cudaGetSymbolAddress((void**)&xl,  g_xl);
    cudaGetSymbolAddress((void**)&wqh, g_wqh); cudaGetSymbolAddress((void**)&wql, g_wql);
    cudaGetSymbolAddress((void**)&wkh, g_wkh); cudaGetSymbolAddress((void**)&wkl, g_wkl);
    cudaGetSymbolAddress((void**)&wvh, g_wvh); cudaGetSymbolAddress((void**)&wvl, g_wvl);
    cudaGetSymbolAddress((void**)&wgh, g_wgh); cudaGetSymbolAddress((void**)&wgl, g_wgl);
    cudaGetSymbolAddress((void**)&woh, g_woh); cudaGetSymbolAddress((void**)&wol, g_wol);
    cudaGetSymbolAddress((void**)&goh, g_goh); cudaGetSymbolAddress((void**)&gol, g_gol);
    cudaGetSymbolAddress((void**)&qbh, g_qbh); cudaGetSymbolAddress((void**)&qbl, g_qbl);
    cudaGetSymbolAddress((void**)&kbh, g_kbh); cudaGetSymbolAddress((void**)&kbl, g_kbl);
    cudaGetSymbolAddress((void**)&vbh, g_vbh); cudaGetSymbolAddress((void**)&vbl, g_vbl);

    SplitArgs sa;
    sa.src[0] = s;   sa.hi[0] = sh;  sa.lo[0] = sl;
    sa.src[1] = kin; sa.hi[1] = xh;  sa.lo[1] = xl;
    sa.src[2] = Wq;  sa.hi[2] = wqh; sa.lo[2] = wql;
    sa.src[3] = Wk;  sa.hi[3] = wkh; sa.lo[3] = wkl;
    sa.src[4] = Wv;  sa.hi[4] = wvh; sa.lo[4] = wvl;
    sa.src[5] = Wg;  sa.hi[5] = wgh; sa.lo[5] = wgl;
    sa.src[6] = Wo;  sa.hi[6] = woh; sa.lo[6] = wol;
    split7<<<dim3(256, 7), 256>>>(sa);

    cudaFuncSetAttribute(gemm_tc4, cudaFuncAttributeMaxDynamicSharedMemorySize, G4_SMEM);
    gemm_tc4<<<dim3(16, 8, 4), 256, G4_SMEM>>>(
        sh, sl, xh, xl, wqh, wql, wkh, wkl, wvh, wvl, wgh, wgl, bq,
        qbh, qbl, kbh, kbl, vbh, vbl, g);

    cudaFuncSetAttribute(zbias_kernel, cudaFuncAttributeMaxDynamicSharedMemorySize, ZB_SMEM);
    zbias_kernel<<<dim3(NI / 2, NJ / 256), 256, ZB_SMEM>>>(bias, Wz, mask, z);

    cudaFuncSetAttribute(attn_mma, cudaFuncAttributeMaxDynamicSharedMemorySize, AT_SMEM);
    attn_mma<<<dim3(NH, NI / 64), 128, AT_SMEM>>>(
        qbh, qbl, kbh, kbl, vbh, vbl, z, g, goh, gol);

    cudaFuncSetAttribute(gemm_out64, cudaFuncAttributeMaxDynamicSharedMemorySize, G64_SMEM);
    gemm_out64<<<dim3(CS / 128, NI / 64), 256, G64_SMEM>>>(goh, gol, woh, wol, out);
}

// round 14
// speedup vs baseline: 1.4782x; 1.0407x over previous
#include <cuda_runtime.h>
#include <cuda_bf16.h>
#include <math.h>
#include <stdint.h>

#define CS 1024
#define CZ 128
#define NH 16
#define HD 64
#define NI 1024
#define NJ 1024
#define NELEM (NI * CS)

// ---------------- scratch (device globals; no allocation allowed) ----------------
__device__ float g_g[NELEM];
__device__ __nv_bfloat16 g_z[(size_t)NH * NI * NJ];   // 32 MB (bf16)

// bf16 hi/lo split buffers (inputs + weights)
__device__ __nv_bfloat16 g_sh[NELEM],  g_sl[NELEM];     // s
__device__ __nv_bfloat16 g_xh[NELEM],  g_xl[NELEM];     // k_in
__device__ __nv_bfloat16 g_wqh[NELEM], g_wql[NELEM];
__device__ __nv_bfloat16 g_wkh[NELEM], g_wkl[NELEM];
__device__ __nv_bfloat16 g_wvh[NELEM], g_wvl[NELEM];
__device__ __nv_bfloat16 g_wgh[NELEM], g_wgl[NELEM];
__device__ __nv_bfloat16 g_woh[NELEM], g_wol[NELEM];
__device__ __nv_bfloat16 g_goh[NELEM], g_gol[NELEM];    // g (*) o  (written by attn epilogue)
// q/k/v hi/lo (written directly by projection epilogue)
__device__ __nv_bfloat16 g_qbh[NELEM], g_qbl[NELEM];
__device__ __nv_bfloat16 g_kbh[NELEM], g_kbl[NELEM];
__device__ __nv_bfloat16 g_vbh[NELEM], g_vbl[NELEM];

// =====================================================================
// helpers (baseline PTX only — NO tcgen05 on this toolchain path)
// =====================================================================
__device__ __forceinline__ uint32_t smem_u32(const void* p) {
    uint32_t a;
    asm("{ .reg .u64 t; cvta.to.shared.u64 t, %1; cvt.u32.u64 %0, t; }"
        : "=r"(a) : "l"(p));
    return a;
}

__device__ __forceinline__ void cp16(uint32_t dst, const void* src) {
    uint64_t g;
    asm("cvta.to.global.u64 %0, %1;" : "=l"(g) : "l"(src));
    asm volatile("cp.async.cg.shared.global [%0], [%1], 16;" :: "r"(dst), "l"(g));
}

__device__ __forceinline__ void ldm_x4(uint32_t* r, uint32_t addr) {
    asm volatile("ldmatrix.sync.aligned.m8n8.x4.shared.b16 {%0,%1,%2,%3}, [%4];"
        : "=r"(r[0]), "=r"(r[1]), "=r"(r[2]), "=r"(r[3]) : "r"(addr));
}

__device__ __forceinline__ void ldm_x4t(uint32_t* r, uint32_t addr) {
    asm volatile("ldmatrix.sync.aligned.m8n8.x4.trans.shared.b16 {%0,%1,%2,%3}, [%4];"
        : "=r"(r[0]), "=r"(r[1]), "=r"(r[2]), "=r"(r[3]) : "r"(addr));
}

__device__ __forceinline__ void mma16816(float* d, const uint32_t* a, const uint32_t* b) {
    asm volatile(
        "mma.sync.aligned.m16n8k16.row.col.f32.bf16.bf16.f32 "
        "{%0,%1,%2,%3}, {%4,%5,%6,%7}, {%8,%9}, {%0,%1,%2,%3};"
        : "+f"(d[0]), "+f"(d[1]), "+f"(d[2]), "+f"(d[3])
        : "r"(a[0]), "r"(a[1]), "r"(a[2]), "r"(a[3]), "r"(b[0]), "r"(b[1]));
}

__device__ __forceinline__ uint32_t swz(uint32_t off) {
    return off ^ ((off >> 3) & 0x70);
}

// FMA-pipe exp (no MUFU): exp(x) = 2^(x*log2e), poly on [-0.5,0.5]
__device__ __forceinline__ float fexp(float x) {
    float t = fmaxf(x * 1.4426950408889634f, -126.0f);
    float zz = t + 12582912.0f;              // 1.5 * 2^23 magic round
    int   ii = __float_as_int(zz) - 0x4B400000;
    float f  = t - (zz - 12582912.0f);
    float p  = 1.3333558146e-3f;
    p = fmaf(p, f, 9.6181291076e-3f);
    p = fmaf(p, f, 5.5504108664e-2f);
    p = fmaf(p, f, 2.4022650696e-1f);
    p = fmaf(p, f, 6.9314718056e-1f);
    p = fmaf(p, f, 1.0f);
    return __int_as_float(__float_as_int(p) + (ii << 23));
}

__device__ __forceinline__ uint32_t pk_hi(float a, float b) {
    __nv_bfloat162 t;
    t.x = __float2bfloat16(a); t.y = __float2bfloat16(b);
    return *(uint32_t*)&t;
}
__device__ __forceinline__ uint32_t pk_lo(float a, float b) {
    __nv_bfloat16 ha = __float2bfloat16(a), hb = __float2bfloat16(b);
    __nv_bfloat162 t;
    t.x = __float2bfloat16(a - __bfloat162float(ha));
    t.y = __float2bfloat16(b - __bfloat162float(hb));
    return *(uint32_t*)&t;
}

// =====================================================================
// split conversion: x -> (hi=bf16(x), lo=bf16(x-hi))
// =====================================================================
struct SplitArgs {
    const float* src[7];
    __nv_bfloat16* hi[7];
    __nv_bfloat16* lo[7];
};

__device__ __forceinline__ void split4(float4 v, __nv_bfloat162* hi2,
                                       __nv_bfloat162* lo2, size_t i) {
    __nv_bfloat16 h0 = __float2bfloat16(v.x);
    __nv_bfloat16 h1 = __float2bfloat16(v.y);
    __nv_bfloat16 h2 = __float2bfloat16(v.z);
    __nv_bfloat16 h3 = __float2bfloat16(v.w);
    __nv_bfloat16 l0 = __float2bfloat16(v.x - __bfloat162float(h0));
    __nv_bfloat16 l1 = __float2bfloat16(v.y - __bfloat162float(h1));
    __nv_bfloat16 l2 = __float2bfloat16(v.z - __bfloat162float(h2));
    __nv_bfloat16 l3 = __float2bfloat16(v.w - __bfloat162float(h3));
    __nv_bfloat162 ph0; ph0.x = h0; ph0.y = h1;
    __nv_bfloat162 ph1; ph1.x = h2; ph1.y = h3;
    __nv_bfloat162 pl0; pl0.x = l0; pl0.y = l1;
    __nv_bfloat162 pl1; pl1.x = l2; pl1.y = l3;
    hi2[2 * i] = ph0; hi2[2 * i + 1] = ph1;
    lo2[2 * i] = pl0; lo2[2 * i + 1] = pl1;
}

__global__ __launch_bounds__(256) void split7(SplitArgs a) {
    const float4* src = (const float4*)a.src[blockIdx.y];
    __nv_bfloat162* hi2 = (__nv_bfloat162*)a.hi[blockIdx.y];
    __nv_bfloat162* lo2 = (__nv_bfloat162*)a.lo[blockIdx.y];
    int t = blockIdx.x * 256 + threadIdx.x;
    for (size_t i = t; i < NELEM / 4; i += 256 * 256)
        split4(src[i], hi2, lo2, i);
}

// =====================================================================
// bf16-split GEMM (projections): 128(M) x 64(N) tiles, BK=64,
// 2-stage cp.async, 48KB/stage -> 97KB/CTA -> co-resides with zbias CTA.
// 8 warps as 4(M:32) x 2(N:32).
// =====================================================================
#define G4_SSZ 49152
#define G4_SMEM (2 * G4_SSZ + 1024)

__device__ __forceinline__ void load_stage_g4(
    uint32_t sbase, int s, int tid,
    const __nv_bfloat16* Ah, const __nv_bfloat16* Al,
    const __nv_bfloat16* Bh, const __nv_bfloat16* Bl,
    int m0, int n0)
{
    uint32_t sb = sbase + (uint32_t)(s & 1) * G4_SSZ;
    int k0 = s * 64;
#pragma unroll
    for (int p = 0; p < 8; p++) {          // A hi/lo: 128 rows x 8 chunks x 2
        int slot = tid + 256 * p;
        int arr = slot >> 10, idx = slot & 1023;
        int row = idx >> 3, ch = idx & 7;
        cp16(sb + (uint32_t)arr * 16384u + swz((uint32_t)(row * 128 + ch * 16)),
             (arr ? Al : Ah) + (size_t)(m0 + row) * CS + k0 + ch * 8);
    }
#pragma unroll
    for (int p = 0; p < 4; p++) {          // B hi/lo: 64 rows x 8 chunks x 2
        int slot = tid + 256 * p;
        int arr = slot >> 9, idx = slot & 511;
        int row = idx >> 3, ch = idx & 7;
        cp16(sb + 32768u + (uint32_t)arr * 8192u + swz((uint32_t)(row * 128 + ch * 16)),
             (arr ? Bl : Bh) + (size_t)(n0 + row) * CS + k0 + ch * 8);
    }
}

template <int MODE, int OUT>   // MODE: 0 plain,1 +bias,2 sigmoid; OUT: 0 fp32, 1 bf16 hi/lo
__device__ void gemm_mma64_core(
    const __nv_bfloat16* Ah, const __nv_bfloat16* Al,
    const __nv_bfloat16* Bh, const __nv_bfloat16* Bl,
    const float* bvec, float* C,
    __nv_bfloat16* Ch, __nv_bfloat16* Cl, int m0, int n0)
{
    extern __shared__ __align__(16) char dsm[];
    const int tid = threadIdx.x;
    uint32_t sbase = smem_u32(dsm);
    sbase = (sbase + 1023u) & ~1023u;

    const int w  = tid >> 5;
    const int ln = tid & 31;
    const int wm = w & 3;        // 4 warps over M: 32 rows each
    const int wn = w >> 2;       // 2 warps over N: 32 cols each

    float acc[2][4][4];
#pragma unroll
    for (int mt = 0; mt < 2; mt++)
#pragma unroll
        for (int nt = 0; nt < 4; nt++)
#pragma unroll
            for (int e = 0; e < 4; e++) acc[mt][nt][e] = 0.f;

    load_stage_g4(sbase, 0, tid, Ah, Al, Bh, Bl, m0, n0);
    asm volatile("cp.async.commit_group;" ::: "memory");

    const int a_row = wm * 32 + (ln & 15);
    const int a_kb  = (ln >> 4) * 16;
    const int b_row = wn * 32 + (ln & 7) + ((ln >> 4) & 1) * 8;
    const int b_kb  = ((ln >> 3) & 1) * 16;

    for (int s = 0; s < 16; s++) {
        if (s + 1 < 16) {
            load_stage_g4(sbase, s + 1, tid, Ah, Al, Bh, Bl, m0, n0);
            asm volatile("cp.async.commit_group;" ::: "memory");
            asm volatile("cp.async.wait_group 1;" ::: "memory");
        } else {
            asm volatile("cp.async.wait_group 0;" ::: "memory");
        }
        __syncthreads();

        uint32_t sb = sbase + (uint32_t)(s & 1) * G4_SSZ;
#pragma unroll
        for (int kk = 0; kk < 4; kk++) {
            uint32_t ah[2][4], al[2][4], bh[4][2], bl[4][2];
#pragma unroll
            for (int mt = 0; mt < 2; mt++) {
                uint32_t off = swz((uint32_t)((a_row + mt * 16) * 128 + kk * 32 + a_kb));
                ldm_x4(ah[mt], sb + off);
                ldm_x4(al[mt], sb + 16384u + off);
            }
#pragma unroll
            for (int np = 0; np < 2; np++) {
                uint32_t off = swz((uint32_t)((b_row + np * 16) * 128 + kk * 32 + b_kb));
                uint32_t t4[4];
                ldm_x4(t4, sb + 32768u + off);
                bh[2 * np][0] = t4[0]; bh[2 * np][1] = t4[1];
                bh[2 * np + 1][0] = t4[2]; bh[2 * np + 1][1] = t4[3];
                ldm_x4(t4, sb + 40960u + off);
                bl[2 * np][0] = t4[0]; bl[2 * np][1] = t4[1];
                bl[2 * np + 1][0] = t4[2]; bl[2 * np + 1][1] = t4[3];
            }
#pragma unroll
            for (int mt = 0; mt < 2; mt++)
#pragma unroll
                for (int nt = 0; nt < 4; nt++) {
                    mma16816(acc[mt][nt], ah[mt], bh[nt]);
                    mma16816(acc[mt][nt], al[mt], bh[nt]);
                    mma16816(acc[mt][nt], ah[mt], bl[nt]);
                }
        }
        __syncthreads();   // all warps done with buf (s&1) before it's reloaded
    }

    const int er = ln >> 2;
    const int ec = (ln & 3) * 2;
#pragma unroll
    for (int mt = 0; mt < 2; mt++) {
#pragma unroll
        for (int nt = 0; nt < 4; nt++) {
            int m = m0 + wm * 32 + mt * 16 + er;
            int n = n0 + wn * 32 + nt * 8 + ec;
#pragma unroll
            for (int half = 0; half < 2; half++) {
                float2 r;
                r.x = acc[mt][nt][2 * half + 0];
                r.y = acc[mt][nt][2 * half + 1];
                if (MODE == 1) { r.x += bvec[n]; r.y += bvec[n + 1]; }
                else if (MODE == 2) {
                    r.x = 1.f / (1.f + __expf(-r.x));
                    r.y = 1.f / (1.f + __expf(-r.y));
                }
                size_t idx = (size_t)(m + half * 8) * CS + n;
                if (OUT == 0) {
                    *(float2*)(C + idx) = r;
                } else {
                    uint32_t uh = pk_hi(r.x, r.y), ul = pk_lo(r.x, r.y);
                    *(uint32_t*)(Ch + idx) = uh;
                    *(uint32_t*)(Cl + idx) = ul;
                }
            }
        }
    }
}

__global__ __launch_bounds__(256, 2) void gemm_tc4(
    const __nv_bfloat16* sh,  const __nv_bfloat16* sl,
    const __nv_bfloat16* xh,  const __nv_bfloat16* xl,
    const __nv_bfloat16* wqh, const __nv_bfloat16* wql,
    const __nv_bfloat16* wkh, const __nv_bfloat16* wkl,
    const __nv_bfloat16* wvh, const __nv_bfloat16* wvl,
    const __nv_bfloat16* wgh, const __nv_bfloat16* wgl,
    const float* bq,
    __nv_bfloat16* qbh, __nv_bfloat16* qbl,
    __nv_bfloat16* kbh, __nv_bfloat16* kbl,
    __nv_bfloat16* vbh, __nv_bfloat16* vbl,
    float* g)
{
    int m0 = blockIdx.y * 128, n0 = blockIdx.x * 64;
    switch (blockIdx.z) {
        case 0:  gemm_mma64_core<1, 1>(sh, sl, wqh, wql, bq, nullptr, qbh, qbl, m0, n0); break;
        case 1:  gemm_mma64_core<0, 1>(xh, xl, wkh, wkl, nullptr, nullptr, kbh, kbl, m0, n0); break;
        case 2:  gemm_mma64_core<0, 1>(xh, xl, wvh, wvl, nullptr, nullptr, vbh, vbl, m0, n0); break;
        default: gemm_mma64_core<2, 0>(sh, sl, wgh, wgl, nullptr, g, nullptr, nullptr, m0, n0); break;
    }
}

// =====================================================================
// Output GEMM: BM=64 x BN=128 tiles -> 128 CTAs (one full wave), 3-stage
// =====================================================================
#define G64_SSZ 49152
#define G64_SMEM (3 * G64_SSZ + 1024)

__device__ __forceinline__ void load_stage64(
    uint32_t sbase, int s, int tid,
    const __nv_bfloat16* Ah, const __nv_bfloat16* Al,
    const __nv_bfloat16* Bh, const __nv_bfloat16* Bl,
    int m0, int n0)
{
    uint32_t sb = sbase + (uint32_t)(s % 3) * G64_SSZ;
    int k0 = s * 64;
#pragma unroll
    for (int p = 0; p < 4; p++) {          // A hi/lo: 64 rows x 8 x 2
        int slot = tid + 256 * p;
        int arr = slot >> 9, idx = slot & 511;
        int row = idx >> 3, ch = idx & 7;
        cp16(sb + (uint32_t)arr * 8192u + swz((uint32_t)(row * 128 + ch * 16)),
             (arr ? Al : Ah) + (size_t)(m0 + row) * CS + k0 + ch * 8);
    }
#pragma unroll
    for (int p = 0; p < 8; p++) {          // B hi/lo: 128 rows x 8 x 2
        int slot = tid + 256 * p;
        int arr = slot >> 10, idx = slot & 1023;
        int row = idx >> 3, ch = idx & 7;
        cp16(sb + 16384u + (uint32_t)arr * 16384u + swz((uint32_t)(row * 128 + ch * 16)),
             (arr ? Bl : Bh) + (size_t)(n0 + row) * CS + k0 + ch * 8);
    }
}

__global__ __launch_bounds__(256, 1) void gemm_out64(
    const __nv_bfloat16* Ah, const __nv_bfloat16* Al,
    const __nv_bfloat16* Bh, const __nv_bfloat16* Bl,
    float* out)
{
    extern __shared__ __align__(16) char dsm[];
    const int tid = threadIdx.x;
    uint32_t sbase = smem_u32(dsm);
    sbase = (sbase + 1023u) & ~1023u;
    const int m0 = blockIdx.y * 64, n0 = blockIdx.x * 128;

    const int w = tid >> 5, ln = tid & 31;
    const int wm = w & 1;        // 2 warps over M (32 rows)
    const int wn = w >> 1;       // 4 warps over N (32 cols)

    float acc[2][4][4];
#pragma unroll
    for (int mt = 0; mt < 2; mt++)
#pragma unroll
        for (int nt = 0; nt < 4; nt++)
#pragma unroll
            for (int e = 0; e < 4; e++) acc[mt][nt][e] = 0.f;

    load_stage64(sbase, 0, tid, Ah, Al, Bh, Bl, m0, n0);
    asm volatile("cp.async.commit_group;" ::: "memory");
    load_stage64(sbase, 1, tid, Ah, Al, Bh, Bl, m0, n0);
    asm volatile("cp.async.commit_group;" ::: "memory");

    const int a_row = wm * 32 + (ln & 15);
    const int a_kb  = (ln >> 4) * 16;
    const int b_row = wn * 32 + (ln & 7) + ((ln >> 4) & 1) * 8;
    const int b_kb  = ((ln >> 3) & 1) * 16;

    for (int s = 0; s < 16; s++) {
        if (s < 15) asm volatile("cp.async.wait_group 1;" ::: "memory");
        else        asm volatile("cp.async.wait_group 0;" ::: "memory");
        __syncthreads();

        uint32_t sb = sbase + (uint32_t)(s % 3) * G64_SSZ;
#pragma unroll
        for (int kk = 0; kk < 4; kk++) {
            uint32_t ah4[2][4], al4[2][4], bh[4][2], bl[4][2];
#pragma unroll
            for (int mt = 0; mt < 2; mt++) {
                uint32_t off = swz((uint32_t)((a_row + mt * 16) * 128 + kk * 32 + a_kb));
                ldm_x4(ah4[mt], sb + off);
                ldm_x4(al4[mt], sb + 8192u + off);
            }
#pragma unroll
            for (int np = 0; np < 2; np++) {
                uint32_t off = swz((uint32_t)((b_row + np * 16) * 128 + kk * 32 + b_kb));
                uint32_t t4[4];
                ldm_x4(t4, sb + 16384u + off);
                bh[2 * np][0] = t4[0]; bh[2 * np][1] = t4[1];
                bh[2 * np + 1][0] = t4[2]; bh[2 * np + 1][1] = t4[3];
                ldm_x4(t4, sb + 32768u + off);
                bl[2 * np][0] = t4[0]; bl[2 * np][1] = t4[1];
                bl[2 * np + 1][0] = t4[2]; bl[2 * np + 1][1] = t4[3];
            }
#pragma unroll
            for (int mt = 0; mt < 2; mt++)
#pragma unroll
                for (int nt = 0; nt < 4; nt++) {
                    mma16816(acc[mt][nt], ah4[mt], bh[nt]);
                    mma16816(acc[mt][nt], al4[mt], bh[nt]);
                    mma16816(acc[mt][nt], ah4[mt], bl[nt]);
                }
        }

        if (s + 2 < 16) {
            load_stage64(sbase, s + 2, tid, Ah, Al, Bh, Bl, m0, n0);
            asm volatile("cp.async.commit_group;" ::: "memory");
        }
    }

    const int er = ln >> 2, ec = (ln & 3) * 2;
#pragma unroll
    for (int mt = 0; mt < 2; mt++)
#pragma unroll
        for (int nt = 0; nt < 4; nt++) {
            int m = m0 + wm * 32 + mt * 16 + er;
            int n = n0 + wn * 32 + nt * 8 + ec;
            float2 r0; r0.x = acc[mt][nt][0]; r0.y = acc[mt][nt][1];
            float2 r1; r1.x = acc[mt][nt][2]; r1.y = acc[mt][nt][3];
            *(float2*)(out + (size_t)m * CS + n) = r0;
            *(float2*)(out + (size_t)(m + 8) * CS + n) = r1;
        }
}

// ---------------- z kernel (writes bf16 z; runs on side stream) ----------------
#define ZB_SMEM ((2 * 256 * 33 + CZ * NH) * 4)
__global__ __launch_bounds__(256) void zbias_kernel(
    const float* __restrict__ bias, const float* __restrict__ Wz,
    const float* __restrict__ mask, __nv_bfloat16* __restrict__ z)
{
    extern __shared__ float sm[];
    float* bs = sm;
    float* wzs = sm + 2 * 256 * 33;

    const int tid = threadIdx.x;
    const int jg = tid & 31;
    const int hg = (tid >> 5) & 3;
    const int ig = tid >> 7;
    const int i0 = blockIdx.x * 2;
    const int j0 = blockIdx.y * 256;

    for (int t = tid; t < CZ * NH; t += 256) wzs[t] = Wz[t];

    float acc[8][4];
#pragma unroll
    for (int kk = 0; kk < 8; kk++)
#pragma unroll
        for (int hh = 0; hh < 4; hh++) acc[kk][hh] = 0.f;

    for (int cc = 0; cc < CZ; cc += 32) {
        __syncthreads();
#pragma unroll
        for (int p = 0; p < 16; p++) {
            int slot = tid + 256 * p;
            int c4 = slot & 7;
            int row = slot >> 3;
            int ii = row >> 8;
            int j = row & 255;
            float4 vv = *(const float4*)(bias +
                ((size_t)(i0 + ii) * NJ + (j0 + j)) * CZ + cc + c4 * 4);
            float* dst = bs + ((size_t)ii * 256 + j) * 33 + c4 * 4;
            dst[0] = vv.x; dst[1] = vv.y; dst[2] = vv.z; dst[3] = vv.w;
        }
        __syncthreads();

#pragma unroll
        for (int c = 0; c < 32; c++) {
            const float* wrow = wzs + (cc + c) * NH + hg * 4;
            float w0 = wrow[0], w1 = wrow[1], w2 = wrow[2], w3 = wrow[3];
#pragma unroll
            for (int kk = 0; kk < 8; kk++) {
                float bv = bs[((size_t)ig * 256 + (jg + 32 * kk)) * 33 + c];
                acc[kk][0] += bv * w0;
                acc[kk][1] += bv * w1;
                acc[kk][2] += bv * w2;
                acc[kk][3] += bv * w3;
            }
        }
    }

    const int i = i0 + ig;
#pragma unroll
    for (int hh = 0; hh < 4; hh++) {
        int h = hg * 4 + hh;
        size_t base = ((size_t)h * NI + i) * NJ;
#pragma unroll
        for (int kk = 0; kk < 8; kk++) {
            int j = j0 + jg + 32 * kk;
            z[base + j] = __float2bfloat16(
                acc[kk][hh] + (1.f - mask[j]) * (-1000000.0f));
        }
    }
}

// =====================================================================
// Flash attention v3: CTA = (head, 64 i-rows), 128 threads (4 warps),
// 2 CTAs/SM. z (bf16) read directly from GMEM.
// =====================================================================
#define AQ_H 0
#define AQ_L 8192
#define ASTG 16384
#define SKH 0
#define SKL 8192
#define SVH 16384
#define SVL 24576
#define SSZ 32768
#define AT_SMEM (ASTG + 2 * SSZ)     /* 81920 */

__device__ __forceinline__ void attn_load_kv(
    uint32_t sb, int stage, int j0, int h, int tid,
    const __nv_bfloat16* kh, const __nv_bfloat16* kl,
    const __nv_bfloat16* vh, const __nv_bfloat16* vl)
{
    uint32_t stg = sb + ASTG + (uint32_t)stage * SSZ;
#pragma unroll
    for (int p = 0; p < 16; p++) {
        int slot = tid + 128 * p;
        int arr = slot >> 9, idx = slot & 511;
        int row = idx >> 3, ch = idx & 7;
        const __nv_bfloat16* base =
            (arr == 0) ? kh : (arr == 1) ? kl : (arr == 2) ? vh : vl;
        cp16(stg + (uint32_t)arr * 8192u + swz((uint32_t)(row * 128 + ch * 16)),
             base + (size_t)(j0 + row) * CS + h * HD + ch * 8);
    }
}

__global__ __launch_bounds__(128, 2) void attn_mma(
    const __nv_bfloat16* __restrict__ qh_g, const __nv_bfloat16* __restrict__ ql_g,
    const __nv_bfloat16* __restrict__ kh_g, const __nv_bfloat16* __restrict__ kl_g,
    const __nv_bfloat16* __restrict__ vh_g, const __nv_bfloat16* __restrict__ vl_g,
    const __nv_bfloat16* __restrict__ z, const float* __restrict__ g,
    __nv_bfloat16* __restrict__ goh, __nv_bfloat16* __restrict__ gol)
{
    extern __shared__ __align__(16) char smra[];
    uint32_t sb = smem_u32(smra);
    const int h = blockIdx.x;
    const int i0 = blockIdx.y * 64;
    const int tid = threadIdx.x;
    const int w = tid >> 5, ln = tid & 31;
    const int r0 = w * 16;               // warp's 16 rows (4 warps x 16 = 64)
    const int er = ln >> 2, ec = (ln & 3) * 2;

    // Q hi/lo (64 x 64 bf16 each): 1024 chunks / 128 threads = 8 per thread
#pragma unroll
    for (int p = 0; p < 8; p++) {
        int slot = tid + 128 * p;
        int arr = slot >> 9, idx = slot & 511;
        int row = idx >> 3, ch = idx & 7;
        cp16(sb + (arr ? AQ_L : AQ_H) + swz((uint32_t)(row * 128 + ch * 16)),
             (arr ? ql_g : qh_g) + (size_t)(i0 + row) * CS + h * HD + ch * 8);
    }
    attn_load_kv(sb, 0, 0, h, tid, kh_g, kl_g, vh_g, vl_g);
    asm volatile("cp.async.commit_group;" ::: "memory");

    // row pointers for direct bf16 z loads (rows rA, rB of this thread)
    const __nv_bfloat16* zA = z + ((size_t)h * NI + i0 + r0 + er) * NJ + ec;
    const __nv_bfloat16* zB = zA + (size_t)8 * NJ;

    float mrow0 = -3.0e38f, mrow1 = -3.0e38f, lrow0 = 0.f, lrow1 = 0.f;
    float accO[8][4];
#pragma unroll
    for (int nt = 0; nt < 8; nt++)
#pragma unroll
        for (int e = 0; e < 4; e++) accO[nt][e] = 0.f;

    for (int jt = 0; jt < 16; jt++) {
        const int j0 = jt * 64;
        if (jt > 0) __syncthreads();     // all warps done with buffer (jt+1)&1
        if (jt + 1 < 16) {
            attn_load_kv(sb, (jt + 1) & 1, (jt + 1) * 64, h, tid,
                         kh_g, kl_g, vh_g, vl_g);
            asm volatile("cp.async.commit_group;" ::: "memory");
            asm volatile("cp.async.wait_group 1;" ::: "memory");
        } else {
            asm volatile("cp.async.wait_group 0;" ::: "memory");
        }
        __syncthreads();

        // issue z loads early (independent; latency hidden under QK MMAs)
        float2 zr0[8], zr1[8];
#pragma unroll
        for (int nt = 0; nt < 8; nt++) {
            __nv_bfloat162 b0 = *(const __nv_bfloat162*)&zA[j0 + nt * 8];
            __nv_bfloat162 b1 = *(const __nv_bfloat162*)&zB[j0 + nt * 8];
            zr0[nt] = __bfloat1622float2(b0);
            zr1[nt] = __bfloat1622float2(b1);
        }

        uint32_t stg = sb + ASTG + (uint32_t)(jt & 1) * SSZ;

        // ---- QK: S = Q @ K^T (3-term) ----
        float accS[8][4];
#pragma unroll
        for (int nt = 0; nt < 8; nt++)
#pragma unroll
            for (int e = 0; e < 4; e++) accS[nt][e] = 0.f;

#pragma unroll
        for (int kk = 0; kk < 4; kk++) {
            uint32_t qh4[4], ql4[4];
            uint32_t offq = swz((uint32_t)((r0 + (ln & 15)) * 128
                                           + kk * 32 + (ln >> 4) * 16));
            ldm_x4(qh4, sb + AQ_H + offq);
            ldm_x4(ql4, sb + AQ_L + offq);
#pragma unroll
            for (int np = 0; np < 4; np++) {
                uint32_t offk = swz((uint32_t)((np * 16 + (ln & 7) + ((ln >> 4) & 1) * 8) * 128
                                               + kk * 32 + ((ln >> 3) & 1) * 16));
                uint32_t th[4], tl[4];
                ldm_x4(th, stg + SKH + offk);
                ldm_x4(tl, stg + SKL + offk);
                mma16816(accS[2 * np], qh4, th);
                mma16816(accS[2 * np], ql4, th);
                mma16816(accS[2 * np], qh4, tl);
                mma16816(accS[2 * np + 1], qh4, th + 2);
                mma16816(accS[2 * np + 1], ql4, th + 2);
                mma16816(accS[2 * np + 1], qh4, tl + 2);
            }
        }

        // ---- scale + z, row max (register softmax) ----
        float mx0 = -3.0e38f, mx1 = -3.0e38f;
#pragma unroll
        for (int nt = 0; nt < 8; nt++) {
            accS[nt][0] = fmaf(accS[nt][0], 0.125f, zr0[nt].x);
            accS[nt][1] = fmaf(accS[nt][1], 0.125f, zr0[nt].y);
            accS[nt][2] = fmaf(accS[nt][2], 0.125f, zr1[nt].x);
            accS[nt][3] = fmaf(accS[nt][3], 0.125f, zr1[nt].y);
            mx0 = fmaxf(mx0, fmaxf(accS[nt][0], accS[nt][1]));
            mx1 = fmaxf(mx1, fmaxf(accS[nt][2], accS[nt][3]));
        }
        mx0 = fmaxf(mx0, __shfl_xor_sync(0xffffffffu, mx0, 1));
        mx0 = fmaxf(mx0, __shfl_xor_sync(0xffffffffu, mx0, 2));
        mx1 = fmaxf(mx1, __shfl_xor_sync(0xffffffffu, mx1, 1));
        mx1 = fmaxf(mx1, __shfl_xor_sync(0xffffffffu, mx1, 2));
        float mn0 = fmaxf(mrow0, mx0), mn1 = fmaxf(mrow1, mx1);
        float sc0 = fexp(mrow0 - mn0), sc1 = fexp(mrow1 - mn1);
        mrow0 = mn0; mrow1 = mn1;

        float sum0 = 0.f, sum1 = 0.f;
#pragma unroll
        for (int nt = 0; nt < 8; nt++) {
            accS[nt][0] = fexp(accS[nt][0] - mn0);
            accS[nt][1] = fexp(accS[nt][1] - mn0);
            accS[nt][2] = fexp(accS[nt][2] - mn1);
            accS[nt][3] = fexp(accS[nt][3] - mn1);
            sum0 += accS[nt][0] + accS[nt][1];
            sum1 += accS[nt][2] + accS[nt][3];
            accO[nt][0] *= sc0; accO[nt][1] *= sc0;
            accO[nt][2] *= sc1; accO[nt][3] *= sc1;
        }
        sum0 += __shfl_xor_sync(0xffffffffu, sum0, 1);
        sum0 += __shfl_xor_sync(0xffffffffu, sum0, 2);
        sum1 += __shfl_xor_sync(0xffffffffu, sum1, 1);
        sum1 += __shfl_xor_sync(0xffffffffu, sum1, 2);
        lrow0 = lrow0 * sc0 + sum0;
        lrow1 = lrow1 * sc1 + sum1;

        // ---- in-register P -> A-frag repack (hi/lo) ----
        uint32_t pah[4][4], pal[4][4];
#pragma unroll
        for (int kk = 0; kk < 4; kk++) {
            pah[kk][0] = pk_hi(accS[2 * kk][0], accS[2 * kk][1]);
            pah[kk][1] = pk_hi(accS[2 * kk][2], accS[2 * kk][3]);
            pah[kk][2] = pk_hi(accS[2 * kk + 1][0], accS[2 * kk + 1][1]);
            pah[kk][3] = pk_hi(accS[2 * kk + 1][2], accS[2 * kk + 1][3]);
            pal[kk][0] = pk_lo(accS[2 * kk][0], accS[2 * kk][1]);
            pal[kk][1] = pk_lo(accS[2 * kk][2], accS[2 * kk][3]);
            pal[kk][2] = pk_lo(accS[2 * kk + 1][0], accS[2 * kk + 1][1]);
            pal[kk][3] = pk_lo(accS[2 * kk + 1][2], accS[2 * kk + 1][3]);
        }

        // ---- PV: O += P @ V (3-term, V via ldmatrix.trans) ----
#pragma unroll
        for (int kk = 0; kk < 4; kk++) {
#pragma unroll
            for (int np = 0; np < 4; np++) {
                uint32_t ov = swz((uint32_t)((kk * 16 + (ln & 7) + ((ln >> 3) & 1) * 8) * 128
                                             + (np * 16 + ((ln >> 4) & 1) * 8) * 2));
                uint32_t th[4], tl[4];
                ldm_x4t(th, stg + SVH + ov);
                ldm_x4t(tl, stg + SVL + ov);
                mma16816(accO[2 * np], pah[kk], th);
                mma16816(accO[2 * np], pal[kk], th);
                mma16816(accO[2 * np], pah[kk], tl);
                mma16816(accO[2 * np + 1], pah[kk], th + 2);
                mma16816(accO[2 * np + 1], pal[kk], th + 2);
                mma16816(accO[2 * np + 1], pah[kk], tl + 2);
            }
        }
    }

    // ---- epilogue: o = accO/l, fused with g (*) . , split to bf16 hi/lo ----
    float inv0 = 1.f / lrow0, inv1 = 1.f / lrow1;
    const int rowA = i0 + r0 + er;
#pragma unroll
    for (int nt = 0; nt < 8; nt++) {
        int col = h * HD + nt * 8 + ec;
        float2 gv0 = *(const float2*)&g[(size_t)rowA * CS + col];
        float2 gv1 = *(const float2*)&g[(size_t)(rowA + 8) * CS + col];
        float x0 = accO[nt][0] * inv0 * gv0.x;
        float x1 = accO[nt][1] * inv0 * gv0.y;
        float x2 = accO[nt][2] * inv1 * gv1.x;
        float x3 = accO[nt][3] * inv1 * gv1.y;
        uint32_t h0 = pk_hi(x0, x1), l0 = pk_lo(x0, x1);
        uint32_t h1 = pk_hi(x2, x3), l1 = pk_lo(x2, x3);
        *(uint32_t*)(goh + (size_t)rowA * CS + col) = h0;
        *(uint32_t*)(gol + (size_t)rowA * CS + col) = l0;
        *(uint32_t*)(goh + (size_t)(rowA + 8) * CS + col) = h1;
        *(uint32_t*)(gol + (size_t)(rowA + 8) * CS + col) = l1;
    }
}

// ---------------- launch: zbias forked on side stream (co-resident now) ----------
extern "C" void kernel_launch(void* const* d_in, const int* in_sizes, int n_in,
                              void* d_out, int out_size)
{
    const float* s    = (const float*)d_in[0];
    const float* kin  = (const float*)d_in[1];
    const float* mask = (const float*)d_in[2];
    const float* bias = (const float*)d_in[3];
    const float* Wq   = (const float*)d_in[4];
    const float* bq   = (const float*)d_in[5];
    const float* Wk   = (const float*)d_in[6];
    const float* Wv   = (const float*)d_in[7];
    const float* Wg   = (const float*)d_in[8];
    const float* Wo   = (const float*)d_in[9];
    const float* Wz   = (const float*)d_in[10];
    float* out = (float*)d_out;

    float* g;
    __nv_bfloat16* z;
    cudaGetSymbolAddress((void**)&g, g_g);
    cudaGetSymbolAddress((void**)&z, g_z);

    __nv_bfloat16 *sh, *sl, *xh, *xl, *wqh, *wql, *wkh, *wkl,
                  *wvh, *wvl, *wgh, *wgl, *woh, *wol, *goh, *gol,
                  *qbh, *qbl, *kbh, *kbl, *vbh, *vbl;
    cudaGetSymbolAddress((void**)&sh,  g_sh);  cudaGetSymbolAddress((void**)&sl,  g_sl);
    cudaGetSymbolAddress((void**)&xh,  g_xh);  cudaGetSymbolAddress((void**)&xl,  g_xl);
    cudaGetSymbolAddress((void**)&wqh, g_wqh); cudaGetSymbolAddress((void**)&wql, g_wql);
    cudaGetSymbolAddress((void**)&wkh, g_wkh); cudaGetSymbolAddress((void**)&wkl, g_wkl);
    cudaGetSymbolAddress((void**)&wvh, g_wvh); cudaGetSymbolAddress((void**)&wvl, g_wvl);
    cudaGetSymbolAddress((void**)&wgh, g_wgh); cudaGetSymbolAddress((void**)&wgl, g_wgl);
    cudaGetSymbolAddress((void**)&woh, g_woh); cudaGetSymbolAddress((void**)&wol, g_wol);
    cudaGetSymbolAddress((void**)&goh, g_goh); cudaGetSymbolAddress((void**)&gol, g_gol);
    cudaGetSymbolAddress((void**)&qbh, g_qbh); cudaGetSymbolAddress((void**)&qbl, g_qbl);
    cudaGetSymbolAddress((void**)&kbh, g_kbh); cudaGetSymbolAddress((void**)&kbl, g_kbl);
    cudaGetSymbolAddress((void**)&vbh, g_vbh); cudaGetSymbolAddress((void**)&vbl, g_vbl);

    // lazy stream/event setup (no device-memory allocation involved)
    static cudaStream_t s2 = nullptr;
    static cudaEvent_t ev1 = nullptr, ev2 = nullptr;
    if (!s2) {
        cudaStreamCreateWithFlags(&s2, cudaStreamNonBlocking);
        cudaEventCreateWithFlags(&ev1, cudaEventDisableTiming);
        cudaEventCreateWithFlags(&ev2, cudaEventDisableTiming);
    }

    // fork: zbias (HBM-bound, 75KB smem) overlaps with split7 + gemm_tc4
    // (compute/L2-bound, 97KB smem) — CTAs co-reside per SM now.
    cudaEventRecord(ev1, 0);
    cudaStreamWaitEvent(s2, ev1, 0);
    cudaFuncSetAttribute(zbias_kernel, cudaFuncAttributeMaxDynamicSharedMemorySize, ZB_SMEM);
    zbias_kernel<<<dim3(NI / 2, NJ / 256), 256, ZB_SMEM, s2>>>(bias, Wz, mask, z);
    cudaEventRecord(ev2, s2);

    // main stream
    SplitArgs sa;
    sa.src[0] = s;   sa.hi[0] = sh;  sa.lo[0] = sl;
    sa.src[1] = kin; sa.hi[1] = xh;  sa.lo[1] = xl;
    sa.src[2] = Wq;  sa.hi[2] = wqh; sa.lo[2] = wql;
    sa.src[3] = Wk;  sa.hi[3] = wkh; sa.lo[3] = wkl;
    sa.src[4] = Wv;  sa.hi[4] = wvh; sa.lo[4] = wvl;
    sa.src[5] = Wg;  sa.hi[5] = wgh; sa.lo[5] = wgl;
    sa.src[6] = Wo;  sa.hi[6] = woh; sa.lo[6] = wol;
    split7<<<dim3(256, 7), 256>>>(sa);

    cudaFuncSetAttribute(gemm_tc4, cudaFuncAttributeMaxDynamicSharedMemorySize, G4_SMEM);
    gemm_tc4<<<dim3(16, 8, 4), 256, G4_SMEM>>>(
        sh, sl, xh, xl, wqh, wql, wkh, wkl, wvh, wvl, wgh, wgl, bq,
        qbh, qbl, kbh, kbl, vbh, vbl, g);

    // join: attn needs z
    cudaStreamWaitEvent(0, ev2, 0);

    cudaFuncSetAttribute(attn_mma, cudaFuncAttributeMaxDynamicSharedMemorySize, AT_SMEM);
    attn_mma<<<dim3(NH, NI / 64), 128, AT_SMEM>>>(
        qbh, qbl, kbh, kbl, vbh, vbl, z, g, goh, gol);

    cudaFuncSetAttribute(gemm_out64, cudaFuncAttributeMaxDynamicSharedMemorySize, G64_SMEM);
    gemm_out64<<<dim3(CS / 128, NI / 64), 256, G64_SMEM>>>(goh, gol, woh, wol, out);
}